// round 1
// baseline (speedup 1.0000x reference)
#include <cuda_runtime.h>
#include <cuda_bf16.h>
#include <math.h>

// ---------------------------------------------------------------------------
// StaticSelfAttention: B=1, S=2048, DIM=5120, H=40, D=128, fp32.
// Pipeline: qkv = hs @ w_qkv + b ; rmsnorm(q|k over DIM) ; rope(q,k) ;
//           flash-attn ; out = O @ w_out + b_out
// ---------------------------------------------------------------------------

#define S_LEN 2048
#define DIM   5120
#define NHEAD 40
#define HDIM  128
#define QKVW  (3*DIM)          // 15360
#define EPS   1e-6f
#define ATT_SCALE 0.08838834764831845f   // 128^-0.5

// Scratch (allocation-free rule: __device__ globals)
__device__ float g_qkv[(size_t)S_LEN * QKVW];     // [S][3*DIM]
__device__ float g_att[(size_t)S_LEN * DIM];      // attention output [S][DIM]

// ===========================================================================
// SGEMM: C[M,N] = A[M,K] @ B[K,N] + bias[N]   (all row-major, dims % tiles==0)
// 128x128 block tile, BK=16, 256 threads, 8x8 per-thread register tile.
// ===========================================================================
#define BM 128
#define BN 128
#define BK 16

__global__ __launch_bounds__(256) void sgemm_bias(
    const float* __restrict__ A, const float* __restrict__ B,
    const float* __restrict__ bias, float* __restrict__ C,
    int M, int N, int K)
{
    __shared__ float As[BK][BM + 4];   // transposed A tile (pad kills store conflicts)
    __shared__ float Bs[BK][BN];

    const int tid = threadIdx.x;
    const int tx = tid & 15, ty = tid >> 4;
    const int row0 = blockIdx.y * BM;
    const int col0 = blockIdx.x * BN;

    float acc[8][8];
    #pragma unroll
    for (int i = 0; i < 8; i++)
        #pragma unroll
        for (int j = 0; j < 8; j++) acc[i][j] = 0.f;

    for (int k0 = 0; k0 < K; k0 += BK) {
        // Load A tile: 128x16 = 512 float4, 2 per thread
        #pragma unroll
        for (int i = 0; i < 2; i++) {
            int f = tid + i * 256;
            int r = f >> 2, c4 = (f & 3) * 4;
            float4 v = *(const float4*)(A + (size_t)(row0 + r) * K + k0 + c4);
            As[c4 + 0][r] = v.x; As[c4 + 1][r] = v.y;
            As[c4 + 2][r] = v.z; As[c4 + 3][r] = v.w;
        }
        // Load B tile: 16x128 = 512 float4, 2 per thread
        #pragma unroll
        for (int i = 0; i < 2; i++) {
            int f = tid + i * 256;
            int r = f >> 5, c4 = (f & 31) * 4;
            *(float4*)(&Bs[r][c4]) =
                *(const float4*)(B + (size_t)(k0 + r) * N + col0 + c4);
        }
        __syncthreads();

        #pragma unroll
        for (int kk = 0; kk < BK; kk++) {
            float a[8], b[8];
            *(float4*)(a)     = *(float4*)(&As[kk][ty * 8]);
            *(float4*)(a + 4) = *(float4*)(&As[kk][ty * 8 + 4]);
            *(float4*)(b)     = *(float4*)(&Bs[kk][tx * 8]);
            *(float4*)(b + 4) = *(float4*)(&Bs[kk][tx * 8 + 4]);
            #pragma unroll
            for (int i = 0; i < 8; i++)
                #pragma unroll
                for (int j = 0; j < 8; j++)
                    acc[i][j] += a[i] * b[j];
        }
        __syncthreads();
    }

    #pragma unroll
    for (int i = 0; i < 8; i++) {
        int r = row0 + ty * 8 + i;
        #pragma unroll
        for (int j = 0; j < 8; j += 4) {
            int c = col0 + tx * 8 + j;
            float4 o;
            o.x = acc[i][j]     + bias[c];
            o.y = acc[i][j + 1] + bias[c + 1];
            o.z = acc[i][j + 2] + bias[c + 2];
            o.w = acc[i][j + 3] + bias[c + 3];
            *(float4*)(C + (size_t)r * N + c) = o;
        }
    }
}

// ===========================================================================
// Fused RMSNorm (over full DIM) + RoPE, in place on q / k slices of g_qkv.
// grid: (S, 2)  blockIdx.y: 0 = q slice, 1 = k slice. 256 threads.
// ===========================================================================
__global__ __launch_bounds__(256) void normrope_kernel(
    float* __restrict__ qkv,
    const float* __restrict__ w_qn, const float* __restrict__ w_kn,
    const float* __restrict__ cosf, const float* __restrict__ sinf)
{
    const int s   = blockIdx.x;
    const int sel = blockIdx.y;                  // 0=q 1=k
    float* row = qkv + (size_t)s * QKVW + sel * DIM;
    const float* w = sel ? w_kn : w_qn;

    const int tid = threadIdx.x;
    const int lane = tid & 31, wid = tid >> 5;
    __shared__ float red[8];
    __shared__ float s_rstd;

    // sum of squares over 5120 floats = 1280 float4
    float ss = 0.f;
    const float4* row4 = (const float4*)row;
    for (int i = tid; i < DIM / 4; i += 256) {
        float4 v = row4[i];
        ss += v.x * v.x + v.y * v.y + v.z * v.z + v.w * v.w;
    }
    #pragma unroll
    for (int o = 16; o; o >>= 1) ss += __shfl_xor_sync(0xffffffffu, ss, o);
    if (lane == 0) red[wid] = ss;
    __syncthreads();
    if (tid == 0) {
        float t = 0.f;
        #pragma unroll
        for (int i = 0; i < 8; i++) t += red[i];
        s_rstd = rsqrtf(t / (float)DIM + EPS);
    }
    __syncthreads();
    const float rstd = s_rstd;

    // rope on pairs: 2560 pairs per row
    const float* crow = cosf + (size_t)s * HDIM;
    const float* srow = sinf + (size_t)s * HDIM;
    for (int p = tid; p < DIM / 2; p += 256) {
        int head = p >> 6;           // p / 64 pairs-per-head
        int t    = p & 63;
        int e0 = head * HDIM + 2 * t;
        float xe = row[e0]     * rstd * w[e0];
        float xo = row[e0 + 1] * rstd * w[e0 + 1];
        float c  = crow[2 * t];
        float sn = srow[2 * t + 1];
        row[e0]     = xe * c - xo * sn;
        row[e0 + 1] = xe * sn + xo * c;
    }
}

// ===========================================================================
// Flash attention, fp32. Br = Bc = 64, 256 threads, one block per (qtile, head).
// Q/K tiles stored d-major with XOR swizzle at float4 granularity so both the
// transposed stores (lanes span d) and the per-d dot-product reads are
// conflict-free. V row-major. S tile stored [col][row] stride 68.
// ===========================================================================
#define FA_BR 64
#define FA_BC 64
#define SS_LD 68

struct FaSmem {
    float Qs[128 * FA_BR];       // swizzled [d][r]
    float Ks[128 * FA_BC];       // swizzled [d][c]
    float Vs[FA_BC * 128];       // row-major [j][d]
    float Ss[FA_BC * SS_LD];     // [c][r], stride 68
    float m_s[FA_BR], l_s[FA_BR], al_s[FA_BR];
};
#define FA_SMEM_BYTES ((int)sizeof(FaSmem))

// float4-slot index for swizzled d-major tile: 16 slots (64 floats) per d row
__device__ __forceinline__ int fa_slot(int d, int r4) {
    return d * 16 + (r4 ^ ((d >> 2) & 15));
}

__global__ __launch_bounds__(256) void fa_kernel(
    const float* __restrict__ qkv, float* __restrict__ O)
{
    extern __shared__ char smraw[];
    FaSmem& sm = *(FaSmem*)smraw;

    const int tid = threadIdx.x;
    const int qt = blockIdx.x, h = blockIdx.y;
    const int q0 = qt * FA_BR;
    const size_t LD = QKVW;
    const int qoff = h * HDIM;
    const int koff = DIM + h * HDIM;
    const int voff = 2 * DIM + h * HDIM;

    // ---- load Q tile (transposed + swizzled) ----
    #pragma unroll
    for (int i = 0; i < 8; i++) {
        int f = tid + i * 256;           // 2048 float4 total
        int r = f >> 5;
        int d4 = (f & 31) * 4;
        float4 v = *(const float4*)(qkv + (size_t)(q0 + r) * LD + qoff + d4);
        int r4 = r >> 2, rm = r & 3;
        int sw = (d4 >> 2) & 15;
        sm.Qs[((d4 + 0) * 16 + (r4 ^ sw)) * 4 + rm] = v.x;
        sm.Qs[((d4 + 1) * 16 + (r4 ^ sw)) * 4 + rm] = v.y;
        sm.Qs[((d4 + 2) * 16 + (r4 ^ sw)) * 4 + rm] = v.z;
        sm.Qs[((d4 + 3) * 16 + (r4 ^ sw)) * 4 + rm] = v.w;
    }
    if (tid < FA_BR) { sm.m_s[tid] = -1e30f; sm.l_s[tid] = 0.f; }

    const int sty = tid >> 4, stx = tid & 15;   // S tile: rows sty*4, cols stx*4
    const int oty = tid >> 4, otx = tid & 15;   // O tile: rows oty*4, cols otx*8
    float acc[4][8];
    #pragma unroll
    for (int i = 0; i < 4; i++)
        #pragma unroll
        for (int j = 0; j < 8; j++) acc[i][j] = 0.f;

    const float4* Q4 = (const float4*)sm.Qs;
    const float4* K4 = (const float4*)sm.Ks;

    for (int kt = 0; kt < S_LEN / FA_BC; kt++) {
        const int kbase = kt * FA_BC;
        __syncthreads();   // prior O-update must finish before K/V overwrite

        // ---- load K (swizzled) and V (row-major) ----
        #pragma unroll
        for (int i = 0; i < 8; i++) {
            int f = tid + i * 256;
            int r = f >> 5;
            int d4 = (f & 31) * 4;
            float4 kv = *(const float4*)(qkv + (size_t)(kbase + r) * LD + koff + d4);
            int r4 = r >> 2, rm = r & 3;
            int sw = (d4 >> 2) & 15;
            sm.Ks[((d4 + 0) * 16 + (r4 ^ sw)) * 4 + rm] = kv.x;
            sm.Ks[((d4 + 1) * 16 + (r4 ^ sw)) * 4 + rm] = kv.y;
            sm.Ks[((d4 + 2) * 16 + (r4 ^ sw)) * 4 + rm] = kv.z;
            sm.Ks[((d4 + 3) * 16 + (r4 ^ sw)) * 4 + rm] = kv.w;
            float4 vv = *(const float4*)(qkv + (size_t)(kbase + r) * LD + voff + d4);
            *(float4*)(&sm.Vs[r * 128 + d4]) = vv;
        }
        __syncthreads();

        // ---- S = Q K^T * scale ----
        float s[4][4];
        #pragma unroll
        for (int i = 0; i < 4; i++)
            #pragma unroll
            for (int j = 0; j < 4; j++) s[i][j] = 0.f;

        #pragma unroll 4
        for (int d = 0; d < 128; d++) {
            float4 qv = Q4[fa_slot(d, sty)];
            float4 kv = K4[fa_slot(d, stx)];
            float qa[4] = {qv.x, qv.y, qv.z, qv.w};
            float kb[4] = {kv.x, kv.y, kv.z, kv.w};
            #pragma unroll
            for (int i = 0; i < 4; i++)
                #pragma unroll
                for (int j = 0; j < 4; j++)
                    s[i][j] += qa[i] * kb[j];
        }
        // write Ss[c][r] (float4 across rows)
        #pragma unroll
        for (int j = 0; j < 4; j++) {
            float4 col;
            col.x = s[0][j] * ATT_SCALE; col.y = s[1][j] * ATT_SCALE;
            col.z = s[2][j] * ATT_SCALE; col.w = s[3][j] * ATT_SCALE;
            *(float4*)(&sm.Ss[(stx * 4 + j) * SS_LD + sty * 4]) = col;
        }
        __syncthreads();

        // ---- online softmax bookkeeping (one thread per row) ----
        if (tid < FA_BR) {
            const int r = tid;
            float mo = sm.m_s[r];
            float mv = mo;
            #pragma unroll 8
            for (int j = 0; j < FA_BC; j++)
                mv = fmaxf(mv, sm.Ss[j * SS_LD + r]);
            float alpha = __expf(mo - mv);
            float lsum = 0.f;
            #pragma unroll 8
            for (int j = 0; j < FA_BC; j++) {
                float p = __expf(sm.Ss[j * SS_LD + r] - mv);
                sm.Ss[j * SS_LD + r] = p;
                lsum += p;
            }
            sm.m_s[r] = mv;
            sm.l_s[r] = sm.l_s[r] * alpha + lsum;
            sm.al_s[r] = alpha;
        }
        __syncthreads();

        // ---- O = O*alpha + P @ V ----
        float al[4];
        #pragma unroll
        for (int i = 0; i < 4; i++) al[i] = sm.al_s[oty * 4 + i];
        #pragma unroll
        for (int i = 0; i < 4; i++)
            #pragma unroll
            for (int j = 0; j < 8; j++) acc[i][j] *= al[i];

        #pragma unroll 4
        for (int j = 0; j < FA_BC; j++) {
            float4 p4 = *(float4*)(&sm.Ss[j * SS_LD + oty * 4]);
            float p[4] = {p4.x, p4.y, p4.z, p4.w};
            float v[8];
            *(float4*)(v)     = *(float4*)(&sm.Vs[j * 128 + otx * 8]);
            *(float4*)(v + 4) = *(float4*)(&sm.Vs[j * 128 + otx * 8 + 4]);
            #pragma unroll
            for (int i = 0; i < 4; i++)
                #pragma unroll
                for (int c = 0; c < 8; c++)
                    acc[i][c] += p[i] * v[c];
        }
    }

    // ---- epilogue: divide by l, write O ----
    #pragma unroll
    for (int i = 0; i < 4; i++) {
        int rr = oty * 4 + i;
        float inv = 1.f / sm.l_s[rr];
        int r = q0 + rr;
        #pragma unroll
        for (int j = 0; j < 8; j += 4) {
            float4 o;
            o.x = acc[i][j]     * inv;
            o.y = acc[i][j + 1] * inv;
            o.z = acc[i][j + 2] * inv;
            o.w = acc[i][j + 3] * inv;
            *(float4*)(O + (size_t)r * DIM + h * HDIM + otx * 8 + j) = o;
        }
    }
}

// ===========================================================================
// kernel_launch
// ===========================================================================
extern "C" void kernel_launch(void* const* d_in, const int* in_sizes, int n_in,
                              void* d_out, int out_size)
{
    const float* hs     = (const float*)d_in[0];
    const float* cosf_  = (const float*)d_in[1];
    const float* sinf_  = (const float*)d_in[2];
    const float* w_qkv  = (const float*)d_in[3];
    const float* b_qkv  = (const float*)d_in[4];
    const float* w_qn   = (const float*)d_in[5];
    const float* w_kn   = (const float*)d_in[6];
    const float* w_out  = (const float*)d_in[7];
    const float* b_out  = (const float*)d_in[8];
    float* out = (float*)d_out;

    float *qkv, *att;
    cudaGetSymbolAddress((void**)&qkv, g_qkv);
    cudaGetSymbolAddress((void**)&att, g_att);

    cudaFuncSetAttribute(fa_kernel,
                         cudaFuncAttributeMaxDynamicSharedMemorySize,
                         FA_SMEM_BYTES);

    // 1) qkv = hs @ w_qkv + b_qkv
    sgemm_bias<<<dim3(QKVW / BN, S_LEN / BM), 256>>>(
        hs, w_qkv, b_qkv, qkv, S_LEN, QKVW, DIM);

    // 2) rmsnorm + rope on q and k slices (in place)
    normrope_kernel<<<dim3(S_LEN, 2), 256>>>(qkv, w_qn, w_kn, cosf_, sinf_);

    // 3) flash attention -> g_att [S, DIM]
    fa_kernel<<<dim3(S_LEN / FA_BR, NHEAD), 256, FA_SMEM_BYTES>>>(qkv, att);

    // 4) out = att @ w_out + b_out
    sgemm_bias<<<dim3(DIM / BN, S_LEN / BM), 256>>>(
        att, w_out, b_out, out, S_LEN, DIM, DIM);
}

// round 6
// speedup vs baseline: 2.0316x; 2.0316x over previous
#include <cuda_runtime.h>
#include <cuda_bf16.h>
#include <cstdint>
#include <math.h>

// ---------------------------------------------------------------------------
// StaticSelfAttention: B=1, S=2048, DIM=5120, H=40, D=128, fp32.
// Round 3: mma.sync bf16 GEMMs with K-concat bf16x3 split (fp32 accuracy).
// (tcgen05 unavailable: harness compiles baseline compute_103 PTX.)
// ---------------------------------------------------------------------------

#define S_LEN 2048
#define DIM   5120
#define NHEAD 40
#define HDIM  128
#define QKVW  (3*DIM)          // 15360
#define KCAT  (3*DIM)          // concat K' = 15360
#define EPS   1e-6f
#define ATT_SCALE 0.08838834764831845f   // 128^-0.5

// -------------------- scratch (__device__ globals; no allocs) --------------
__device__ float g_qkv[(size_t)S_LEN * QKVW];
__device__ float g_att[(size_t)S_LEN * DIM];
__device__ __nv_bfloat16 g_hsC [(size_t)S_LEN * KCAT];   // [hi | hi | lo]
__device__ __nv_bfloat16 g_attC[(size_t)S_LEN * KCAT];
__device__ __nv_bfloat16 g_wqkvC[(size_t)QKVW * KCAT];   // [N][ hi | lo | hi ]
__device__ __nv_bfloat16 g_woutC[(size_t)DIM  * KCAT];

// -------------------- PTX helpers (baseline ISA only) ----------------------
__device__ __forceinline__ uint32_t smem_u32(const void* p) {
    uint32_t a;
    asm("{ .reg .u64 t; cvta.to.shared.u64 t, %1; cvt.u32.u64 %0, t; }"
        : "=r"(a) : "l"(p));
    return a;
}
__device__ __forceinline__ void cp16(uint32_t dst, const void* src) {
    asm volatile("cp.async.cg.shared.global [%0], [%1], 16;\n"
                 :: "r"(dst), "l"(src));
}
#define CP_COMMIT() asm volatile("cp.async.commit_group;\n" ::: "memory")
#define CP_WAIT2()  asm volatile("cp.async.wait_group 2;\n" ::: "memory")

__device__ __forceinline__ void ldm_x4(uint32_t* r, uint32_t a) {
    asm volatile("ldmatrix.sync.aligned.m8n8.x4.shared.b16 {%0,%1,%2,%3}, [%4];\n"
                 : "=r"(r[0]), "=r"(r[1]), "=r"(r[2]), "=r"(r[3]) : "r"(a));
}
__device__ __forceinline__ void mma_bf16(float* d, const uint32_t* a,
                                         const uint32_t* b) {
    asm volatile(
        "mma.sync.aligned.m16n8k16.row.col.f32.bf16.bf16.f32 "
        "{%0,%1,%2,%3}, {%4,%5,%6,%7}, {%8,%9}, {%0,%1,%2,%3};\n"
        : "+f"(d[0]), "+f"(d[1]), "+f"(d[2]), "+f"(d[3])
        : "r"(a[0]), "r"(a[1]), "r"(a[2]), "r"(a[3]), "r"(b[0]), "r"(b[1]));
}

// ===========================================================================
// Pre-pass 1: fp32 [M][DIM] -> bf16 concat [M][KCAT] = [hi | hi | lo]
// ===========================================================================
__global__ __launch_bounds__(256) void convert_cat(
    const float* __restrict__ X, __nv_bfloat16* __restrict__ Y, int M)
{
    const int total = M * (DIM / 4);
    for (int i = blockIdx.x * 256 + threadIdx.x; i < total;
         i += gridDim.x * 256) {
        int row = i / (DIM / 4);
        int c4  = (i % (DIM / 4)) * 4;
        float4 v = ((const float4*)X)[i];
        __nv_bfloat16 h0 = __float2bfloat16(v.x);
        __nv_bfloat16 h1 = __float2bfloat16(v.y);
        __nv_bfloat16 h2 = __float2bfloat16(v.z);
        __nv_bfloat16 h3 = __float2bfloat16(v.w);
        __nv_bfloat162 hp0; hp0.x = h0; hp0.y = h1;
        __nv_bfloat162 hp1; hp1.x = h2; hp1.y = h3;
        __nv_bfloat162 lp0, lp1;
        lp0.x = __float2bfloat16(v.x - __bfloat162float(h0));
        lp0.y = __float2bfloat16(v.y - __bfloat162float(h1));
        lp1.x = __float2bfloat16(v.z - __bfloat162float(h2));
        lp1.y = __float2bfloat16(v.w - __bfloat162float(h3));
        __nv_bfloat16* yr = Y + (size_t)row * KCAT;
        *(__nv_bfloat162*)(yr + c4)     = hp0;
        *(__nv_bfloat162*)(yr + c4 + 2) = hp1;
        *(__nv_bfloat162*)(yr + DIM + c4)     = hp0;
        *(__nv_bfloat162*)(yr + DIM + c4 + 2) = hp1;
        *(__nv_bfloat162*)(yr + 2*DIM + c4)     = lp0;
        *(__nv_bfloat162*)(yr + 2*DIM + c4 + 2) = lp1;
    }
}

// ===========================================================================
// Pre-pass 2: W[K=DIM][N] fp32 -> T[N][KCAT] bf16 = [hi | lo | hi]
// ===========================================================================
__global__ void transpose_cat(const float* __restrict__ W,
                              __nv_bfloat16* __restrict__ T, int N)
{
    __shared__ float t[32][33];
    const int n0 = blockIdx.x * 32, k0 = blockIdx.y * 32;
    const int x = threadIdx.x, y = threadIdx.y;   // 32 x 8
    #pragma unroll
    for (int i = 0; i < 32; i += 8)
        t[y + i][x] = W[(size_t)(k0 + y + i) * N + n0 + x];
    __syncthreads();
    #pragma unroll
    for (int i = 0; i < 32; i += 8) {
        float v = t[x][y + i];                    // k-local = x, n-local = y+i
        __nv_bfloat16 h = __float2bfloat16(v);
        __nv_bfloat16 l = __float2bfloat16(v - __bfloat162float(h));
        size_t base = (size_t)(n0 + y + i) * KCAT + k0 + x;
        T[base]          = h;
        T[base + DIM]    = l;
        T[base + 2*DIM]  = h;
    }
}

// ===========================================================================
// mma.sync bf16 GEMM: C[M,N] = A[M,K'] @ Bm[N,K']^T + bias
//   CTA 128x128, BK=32, 4 warps (warp tile 64x64), 4-stage cp.async pipeline.
//   smem tile per operand: 128 rows x 64B, XOR-swizzled 16B chunks.
//   grid = (M/128, N/128), blockIdx.x = M (fast) for L2 reuse of B.
// ===========================================================================
#define G_BK      32
#define G_STAGES  4
#define G_STAGE_B 16384                     // A 8KB + B 8KB
#define G_SMEM    (G_STAGES * G_STAGE_B)    // 64KB

__device__ __forceinline__ uint32_t sw_off(int r, int c) {
    return (uint32_t)(((r << 2) | (c ^ ((r >> 1) & 3))) << 4);
}

__global__ __launch_bounds__(128, 2) void gemm_mma(
    const __nv_bfloat16* __restrict__ A, const __nv_bfloat16* __restrict__ Bm,
    const float* __restrict__ bias, float* __restrict__ C, int N, int K)
{
    extern __shared__ char smraw[];
    const uint32_t sbase = smem_u32(smraw);

    const int tid = threadIdx.x, lane = tid & 31, wid = tid >> 5;
    const int row0 = blockIdx.x * 128;
    const int col0 = blockIdx.y * 128;
    const int mw = (wid >> 1) * 64;        // warp M offset in CTA tile
    const int nw = (wid & 1) * 64;         // warp N offset
    const int sub = lane >> 3, l7 = lane & 7;

    float acc[4][8][4];
    #pragma unroll
    for (int i = 0; i < 4; i++)
        #pragma unroll
        for (int j = 0; j < 8; j++)
            #pragma unroll
            for (int q = 0; q < 4; q++) acc[i][j][q] = 0.f;

    const int NIT = K / G_BK;

    // -------- stage loader: 512 A-chunks + 512 B-chunks of 16B, 128 thr ----
    auto load_stage = [&](int st, int k0) {
        const uint32_t sA = sbase + st * G_STAGE_B;
        const uint32_t sB = sA + 8192;
        #pragma unroll
        for (int i = 0; i < 4; i++) {
            int f = tid + i * 128;          // 0..511
            int r = f >> 2, c = f & 3;
            uint32_t so = sw_off(r, c);
            cp16(sA + so, A  + (size_t)(row0 + r) * K + k0 + c * 8);
            cp16(sB + so, Bm + (size_t)(col0 + r) * K + k0 + c * 8);
        }
    };

    #pragma unroll
    for (int s = 0; s < G_STAGES - 1; s++) { load_stage(s, s * G_BK); CP_COMMIT(); }

    #pragma unroll 1
    for (int it = 0; it < NIT; it++) {
        CP_WAIT2();
        __syncthreads();
        const uint32_t uA = sbase + (it & 3) * G_STAGE_B;
        const uint32_t uB = uA + 8192;

        #pragma unroll
        for (int kk = 0; kk < 2; kk++) {
            const int c0 = kk * 2;
            uint32_t a[4][4], b[4][4];
            #pragma unroll
            for (int i = 0; i < 4; i++) {
                int r = mw + i * 16 + ((sub & 1) << 3) + l7;
                int c = c0 + (sub >> 1);
                ldm_x4(a[i], uA + sw_off(r, c));
            }
            #pragma unroll
            for (int p = 0; p < 4; p++) {
                int r = nw + p * 16 + ((sub >> 1) << 3) + l7;
                int c = c0 + (sub & 1);
                ldm_x4(b[p], uB + sw_off(r, c));
            }
            #pragma unroll
            for (int i = 0; i < 4; i++)
                #pragma unroll
                for (int j = 0; j < 8; j++)
                    mma_bf16(acc[i][j], a[i], &b[j >> 1][(j & 1) * 2]);
        }

        const int nld = it + G_STAGES - 1;
        if (nld < NIT) load_stage(nld & 3, nld * G_BK);
        CP_COMMIT();
    }

    // -------- epilogue ------------------------------------------------------
    const int g = lane >> 2, tq = lane & 3;
    #pragma unroll
    for (int i = 0; i < 4; i++) {
        int r = row0 + mw + i * 16 + g;
        #pragma unroll
        for (int j = 0; j < 8; j++) {
            int c = col0 + nw + j * 8 + tq * 2;
            float bx = bias[c], by = bias[c + 1];
            float2 o0; o0.x = acc[i][j][0] + bx; o0.y = acc[i][j][1] + by;
            float2 o1; o1.x = acc[i][j][2] + bx; o1.y = acc[i][j][3] + by;
            *(float2*)(C + (size_t)r * N + c)       = o0;
            *(float2*)(C + (size_t)(r + 8) * N + c) = o1;
        }
    }
}

// ===========================================================================
// Fused RMSNorm (over full DIM) + RoPE, in place on q / k slices of g_qkv.
// ===========================================================================
__global__ __launch_bounds__(256) void normrope_kernel(
    float* __restrict__ qkv,
    const float* __restrict__ w_qn, const float* __restrict__ w_kn,
    const float* __restrict__ cosf, const float* __restrict__ sinf)
{
    const int s   = blockIdx.x;
    const int sel = blockIdx.y;                  // 0=q 1=k
    float* row = qkv + (size_t)s * QKVW + sel * DIM;
    const float* w = sel ? w_kn : w_qn;

    const int tid = threadIdx.x;
    const int lane = tid & 31, wid = tid >> 5;
    __shared__ float red[8];
    __shared__ float s_rstd;

    float ss = 0.f;
    const float4* row4 = (const float4*)row;
    for (int i = tid; i < DIM / 4; i += 256) {
        float4 v = row4[i];
        ss += v.x * v.x + v.y * v.y + v.z * v.z + v.w * v.w;
    }
    #pragma unroll
    for (int o = 16; o; o >>= 1) ss += __shfl_xor_sync(0xffffffffu, ss, o);
    if (lane == 0) red[wid] = ss;
    __syncthreads();
    if (tid == 0) {
        float t = 0.f;
        #pragma unroll
        for (int i = 0; i < 8; i++) t += red[i];
        s_rstd = rsqrtf(t / (float)DIM + EPS);
    }
    __syncthreads();
    const float rstd = s_rstd;

    const float* crow = cosf + (size_t)s * HDIM;
    const float* srow = sinf + (size_t)s * HDIM;
    for (int p = tid; p < DIM / 2; p += 256) {
        int head = p >> 6;
        int t    = p & 63;
        int e0 = head * HDIM + 2 * t;
        float xe = row[e0]     * rstd * w[e0];
        float xo = row[e0 + 1] * rstd * w[e0 + 1];
        float c  = crow[2 * t];
        float sn = srow[2 * t + 1];
        row[e0]     = xe * c - xo * sn;
        row[e0 + 1] = xe * sn + xo * c;
    }
}

// ===========================================================================
// Flash attention, fp32 SIMT (round-1 version; tensorize next round).
// ===========================================================================
#define FA_BR 64
#define FA_BC 64
#define SS_LD 68

struct FaSmem {
    float Qs[128 * FA_BR];
    float Ks[128 * FA_BC];
    float Vs[FA_BC * 128];
    float Ss[FA_BC * SS_LD];
    float m_s[FA_BR], l_s[FA_BR], al_s[FA_BR];
};
#define FA_SMEM_BYTES ((int)sizeof(FaSmem))

__device__ __forceinline__ int fa_slot(int d, int r4) {
    return d * 16 + (r4 ^ ((d >> 2) & 15));
}

__global__ __launch_bounds__(256) void fa_kernel(
    const float* __restrict__ qkv, float* __restrict__ O)
{
    extern __shared__ char smraw[];
    FaSmem& sm = *(FaSmem*)smraw;

    const int tid = threadIdx.x;
    const int qt = blockIdx.x, h = blockIdx.y;
    const int q0 = qt * FA_BR;
    const size_t LD = QKVW;
    const int qoff = h * HDIM;
    const int koff = DIM + h * HDIM;
    const int voff = 2 * DIM + h * HDIM;

    #pragma unroll
    for (int i = 0; i < 8; i++) {
        int f = tid + i * 256;
        int r = f >> 5;
        int d4 = (f & 31) * 4;
        float4 v = *(const float4*)(qkv + (size_t)(q0 + r) * LD + qoff + d4);
        int r4 = r >> 2, rm = r & 3;
        int sw = (d4 >> 2) & 15;
        sm.Qs[((d4 + 0) * 16 + (r4 ^ sw)) * 4 + rm] = v.x;
        sm.Qs[((d4 + 1) * 16 + (r4 ^ sw)) * 4 + rm] = v.y;
        sm.Qs[((d4 + 2) * 16 + (r4 ^ sw)) * 4 + rm] = v.z;
        sm.Qs[((d4 + 3) * 16 + (r4 ^ sw)) * 4 + rm] = v.w;
    }
    if (tid < FA_BR) { sm.m_s[tid] = -1e30f; sm.l_s[tid] = 0.f; }

    const int sty = tid >> 4, stx = tid & 15;
    const int oty = tid >> 4, otx = tid & 15;
    float acc[4][8];
    #pragma unroll
    for (int i = 0; i < 4; i++)
        #pragma unroll
        for (int j = 0; j < 8; j++) acc[i][j] = 0.f;

    const float4* Q4 = (const float4*)sm.Qs;
    const float4* K4 = (const float4*)sm.Ks;

    for (int kt = 0; kt < S_LEN / FA_BC; kt++) {
        const int kbase = kt * FA_BC;
        __syncthreads();

        #pragma unroll
        for (int i = 0; i < 8; i++) {
            int f = tid + i * 256;
            int r = f >> 5;
            int d4 = (f & 31) * 4;
            float4 kv = *(const float4*)(qkv + (size_t)(kbase + r) * LD + koff + d4);
            int r4 = r >> 2, rm = r & 3;
            int sw = (d4 >> 2) & 15;
            sm.Ks[((d4 + 0) * 16 + (r4 ^ sw)) * 4 + rm] = kv.x;
            sm.Ks[((d4 + 1) * 16 + (r4 ^ sw)) * 4 + rm] = kv.y;
            sm.Ks[((d4 + 2) * 16 + (r4 ^ sw)) * 4 + rm] = kv.z;
            sm.Ks[((d4 + 3) * 16 + (r4 ^ sw)) * 4 + rm] = kv.w;
            float4 vv = *(const float4*)(qkv + (size_t)(kbase + r) * LD + voff + d4);
            *(float4*)(&sm.Vs[r * 128 + d4]) = vv;
        }
        __syncthreads();

        float s[4][4];
        #pragma unroll
        for (int i = 0; i < 4; i++)
            #pragma unroll
            for (int j = 0; j < 4; j++) s[i][j] = 0.f;

        #pragma unroll 4
        for (int d = 0; d < 128; d++) {
            float4 qv = Q4[fa_slot(d, sty)];
            float4 kv = K4[fa_slot(d, stx)];
            float qa[4] = {qv.x, qv.y, qv.z, qv.w};
            float kb[4] = {kv.x, kv.y, kv.z, kv.w};
            #pragma unroll
            for (int i = 0; i < 4; i++)
                #pragma unroll
                for (int j = 0; j < 4; j++)
                    s[i][j] += qa[i] * kb[j];
        }
        #pragma unroll
        for (int j = 0; j < 4; j++) {
            float4 col;
            col.x = s[0][j] * ATT_SCALE; col.y = s[1][j] * ATT_SCALE;
            col.z = s[2][j] * ATT_SCALE; col.w = s[3][j] * ATT_SCALE;
            *(float4*)(&sm.Ss[(stx * 4 + j) * SS_LD + sty * 4]) = col;
        }
        __syncthreads();

        if (tid < FA_BR) {
            const int r = tid;
            float mo = sm.m_s[r];
            float mv = mo;
            #pragma unroll 8
            for (int j = 0; j < FA_BC; j++)
                mv = fmaxf(mv, sm.Ss[j * SS_LD + r]);
            float alpha = __expf(mo - mv);
            float lsum = 0.f;
            #pragma unroll 8
            for (int j = 0; j < FA_BC; j++) {
                float p = __expf(sm.Ss[j * SS_LD + r] - mv);
                sm.Ss[j * SS_LD + r] = p;
                lsum += p;
            }
            sm.m_s[r] = mv;
            sm.l_s[r] = sm.l_s[r] * alpha + lsum;
            sm.al_s[r] = alpha;
        }
        __syncthreads();

        float al[4];
        #pragma unroll
        for (int i = 0; i < 4; i++) al[i] = sm.al_s[oty * 4 + i];
        #pragma unroll
        for (int i = 0; i < 4; i++)
            #pragma unroll
            for (int j = 0; j < 8; j++) acc[i][j] *= al[i];

        #pragma unroll 4
        for (int j = 0; j < FA_BC; j++) {
            float4 p4 = *(float4*)(&sm.Ss[j * SS_LD + oty * 4]);
            float p[4] = {p4.x, p4.y, p4.z, p4.w};
            float v[8];
            *(float4*)(v)     = *(float4*)(&sm.Vs[j * 128 + otx * 8]);
            *(float4*)(v + 4) = *(float4*)(&sm.Vs[j * 128 + otx * 8 + 4]);
            #pragma unroll
            for (int i = 0; i < 4; i++)
                #pragma unroll
                for (int c = 0; c < 8; c++)
                    acc[i][c] += p[i] * v[c];
        }
    }

    #pragma unroll
    for (int i = 0; i < 4; i++) {
        int rr = oty * 4 + i;
        float inv = 1.f / sm.l_s[rr];
        int r = q0 + rr;
        #pragma unroll
        for (int j = 0; j < 8; j += 4) {
            float4 o;
            o.x = acc[i][j]     * inv;
            o.y = acc[i][j + 1] * inv;
            o.z = acc[i][j + 2] * inv;
            o.w = acc[i][j + 3] * inv;
            *(float4*)(O + (size_t)r * DIM + h * HDIM + otx * 8 + j) = o;
        }
    }
}

// ===========================================================================
// kernel_launch
// ===========================================================================
extern "C" void kernel_launch(void* const* d_in, const int* in_sizes, int n_in,
                              void* d_out, int out_size)
{
    const float* hs     = (const float*)d_in[0];
    const float* cosf_  = (const float*)d_in[1];
    const float* sinf_  = (const float*)d_in[2];
    const float* w_qkv  = (const float*)d_in[3];
    const float* b_qkv  = (const float*)d_in[4];
    const float* w_qn   = (const float*)d_in[5];
    const float* w_kn   = (const float*)d_in[6];
    const float* w_out  = (const float*)d_in[7];
    const float* b_out  = (const float*)d_in[8];
    float* out = (float*)d_out;

    float *qkv, *att;
    __nv_bfloat16 *hsC, *attC, *wqkvC, *woutC;
    cudaGetSymbolAddress((void**)&qkv,   g_qkv);
    cudaGetSymbolAddress((void**)&att,   g_att);
    cudaGetSymbolAddress((void**)&hsC,   g_hsC);
    cudaGetSymbolAddress((void**)&attC,  g_attC);
    cudaGetSymbolAddress((void**)&wqkvC, g_wqkvC);
    cudaGetSymbolAddress((void**)&woutC, g_woutC);

    cudaFuncSetAttribute(fa_kernel,
                         cudaFuncAttributeMaxDynamicSharedMemorySize, FA_SMEM_BYTES);
    cudaFuncSetAttribute(gemm_mma,
                         cudaFuncAttributeMaxDynamicSharedMemorySize, G_SMEM);

    // --- pre-passes: weight transposes + input concat-split ---
    transpose_cat<<<dim3(QKVW/32, DIM/32), dim3(32,8)>>>(w_qkv, wqkvC, QKVW);
    transpose_cat<<<dim3(DIM/32,  DIM/32), dim3(32,8)>>>(w_out, woutC, DIM);
    convert_cat<<<2048, 256>>>(hs, hsC, S_LEN);

    // --- qkv = hs @ w_qkv + b ---
    gemm_mma<<<dim3(S_LEN/128, QKVW/128), 128, G_SMEM>>>(
        hsC, wqkvC, b_qkv, qkv, QKVW, KCAT);

    // --- rmsnorm + rope ---
    normrope_kernel<<<dim3(S_LEN, 2), 256>>>(qkv, w_qn, w_kn, cosf_, sinf_);

    // --- flash attention ---
    fa_kernel<<<dim3(S_LEN/FA_BR, NHEAD), 256, FA_SMEM_BYTES>>>(qkv, att);

    // --- out = att @ w_out + b ---
    convert_cat<<<2048, 256>>>(att, attC, S_LEN);
    gemm_mma<<<dim3(S_LEN/128, DIM/128), 128, G_SMEM>>>(
        attC, woutC, b_out, out, DIM, KCAT);
}

// round 7
// speedup vs baseline: 3.5794x; 1.7619x over previous
#include <cuda_runtime.h>
#include <cuda_bf16.h>
#include <cuda_fp16.h>
#include <cstdint>
#include <math.h>

// ---------------------------------------------------------------------------
// StaticSelfAttention: B=1, S=2048, DIM=5120, H=40, D=128, fp32.
// Round 7: mma.sync bf16x3 GEMMs + tensorized flash attention
//          (QK^T bf16x3 concat, PV fp16, register-resident softmax).
// ---------------------------------------------------------------------------

#define S_LEN 2048
#define DIM   5120
#define NHEAD 40
#define HDIM  128
#define QKVW  (3*DIM)          // 15360
#define KCAT  (3*DIM)          // concat K' = 15360
#define EPS   1e-6f
#define ATT_SCALE 0.08838834764831845f   // 128^-0.5

// -------------------- scratch (__device__ globals; no allocs) --------------
__device__ float g_qkv[(size_t)S_LEN * QKVW];
__device__ __nv_bfloat16 g_hsC [(size_t)S_LEN * KCAT];    // [hi | hi | lo]
__device__ __nv_bfloat16 g_attC[(size_t)S_LEN * KCAT];    // [hi | hi | lo]
__device__ __nv_bfloat16 g_wqkvC[(size_t)QKVW * KCAT];    // [N][ hi | lo | hi ]
__device__ __nv_bfloat16 g_woutC[(size_t)DIM  * KCAT];
__device__ __nv_bfloat16 g_qH[(size_t)S_LEN * NHEAD * 384];  // [s][h][hi|hi|lo]
__device__ __nv_bfloat16 g_kH[(size_t)S_LEN * NHEAD * 384];  // [s][h][hi|lo|hi]
__device__ __half        g_vH[(size_t)S_LEN * DIM];          // [s][h][d] fp16

// -------------------- PTX helpers (baseline ISA only) ----------------------
__device__ __forceinline__ uint32_t smem_u32(const void* p) {
    uint32_t a;
    asm("{ .reg .u64 t; cvta.to.shared.u64 t, %1; cvt.u32.u64 %0, t; }"
        : "=r"(a) : "l"(p));
    return a;
}
__device__ __forceinline__ void cp16(uint32_t dst, const void* src) {
    asm volatile("cp.async.cg.shared.global [%0], [%1], 16;\n"
                 :: "r"(dst), "l"(src));
}
#define CP_COMMIT() asm volatile("cp.async.commit_group;\n" ::: "memory")
#define CP_WAIT2()  asm volatile("cp.async.wait_group 2;\n" ::: "memory")
#define CP_WAIT1()  asm volatile("cp.async.wait_group 1;\n" ::: "memory")

__device__ __forceinline__ void ldm_x4(uint32_t* r, uint32_t a) {
    asm volatile("ldmatrix.sync.aligned.m8n8.x4.shared.b16 {%0,%1,%2,%3}, [%4];\n"
                 : "=r"(r[0]), "=r"(r[1]), "=r"(r[2]), "=r"(r[3]) : "r"(a));
}
__device__ __forceinline__ void ldm_x4t(uint32_t* r, uint32_t a) {
    asm volatile("ldmatrix.sync.aligned.m8n8.x4.trans.shared.b16 {%0,%1,%2,%3}, [%4];\n"
                 : "=r"(r[0]), "=r"(r[1]), "=r"(r[2]), "=r"(r[3]) : "r"(a));
}
__device__ __forceinline__ void mma_bf16(float* d, const uint32_t* a,
                                         const uint32_t* b) {
    asm volatile(
        "mma.sync.aligned.m16n8k16.row.col.f32.bf16.bf16.f32 "
        "{%0,%1,%2,%3}, {%4,%5,%6,%7}, {%8,%9}, {%0,%1,%2,%3};\n"
        : "+f"(d[0]), "+f"(d[1]), "+f"(d[2]), "+f"(d[3])
        : "r"(a[0]), "r"(a[1]), "r"(a[2]), "r"(a[3]), "r"(b[0]), "r"(b[1]));
}
__device__ __forceinline__ void mma_f16(float* d, const uint32_t* a,
                                        const uint32_t* b) {
    asm volatile(
        "mma.sync.aligned.m16n8k16.row.col.f32.f16.f16.f32 "
        "{%0,%1,%2,%3}, {%4,%5,%6,%7}, {%8,%9}, {%0,%1,%2,%3};\n"
        : "+f"(d[0]), "+f"(d[1]), "+f"(d[2]), "+f"(d[3])
        : "r"(a[0]), "r"(a[1]), "r"(a[2]), "r"(a[3]), "r"(b[0]), "r"(b[1]));
}
__device__ __forceinline__ uint32_t f22h2(float x, float y) {
    __half2 t = __floats2half2_rn(x, y);
    return *reinterpret_cast<uint32_t*>(&t);
}

// ===========================================================================
// Pre-pass 1: fp32 [M][DIM] -> bf16 concat [M][KCAT] = [hi | hi | lo]
// ===========================================================================
__global__ __launch_bounds__(256) void convert_cat(
    const float* __restrict__ X, __nv_bfloat16* __restrict__ Y, int M)
{
    const int total = M * (DIM / 4);
    for (int i = blockIdx.x * 256 + threadIdx.x; i < total;
         i += gridDim.x * 256) {
        int row = i / (DIM / 4);
        int c4  = (i % (DIM / 4)) * 4;
        float4 v = ((const float4*)X)[i];
        __nv_bfloat16 h0 = __float2bfloat16(v.x);
        __nv_bfloat16 h1 = __float2bfloat16(v.y);
        __nv_bfloat16 h2 = __float2bfloat16(v.z);
        __nv_bfloat16 h3 = __float2bfloat16(v.w);
        __nv_bfloat162 hp0; hp0.x = h0; hp0.y = h1;
        __nv_bfloat162 hp1; hp1.x = h2; hp1.y = h3;
        __nv_bfloat162 lp0, lp1;
        lp0.x = __float2bfloat16(v.x - __bfloat162float(h0));
        lp0.y = __float2bfloat16(v.y - __bfloat162float(h1));
        lp1.x = __float2bfloat16(v.z - __bfloat162float(h2));
        lp1.y = __float2bfloat16(v.w - __bfloat162float(h3));
        __nv_bfloat16* yr = Y + (size_t)row * KCAT;
        *(__nv_bfloat162*)(yr + c4)     = hp0;
        *(__nv_bfloat162*)(yr + c4 + 2) = hp1;
        *(__nv_bfloat162*)(yr + DIM + c4)     = hp0;
        *(__nv_bfloat162*)(yr + DIM + c4 + 2) = hp1;
        *(__nv_bfloat162*)(yr + 2*DIM + c4)     = lp0;
        *(__nv_bfloat162*)(yr + 2*DIM + c4 + 2) = lp1;
    }
}

// ===========================================================================
// Pre-pass 2: W[K=DIM][N] fp32 -> T[N][KCAT] bf16 = [hi | lo | hi]
// ===========================================================================
__global__ void transpose_cat(const float* __restrict__ W,
                              __nv_bfloat16* __restrict__ T, int N)
{
    __shared__ float t[32][33];
    const int n0 = blockIdx.x * 32, k0 = blockIdx.y * 32;
    const int x = threadIdx.x, y = threadIdx.y;   // 32 x 8
    #pragma unroll
    for (int i = 0; i < 32; i += 8)
        t[y + i][x] = W[(size_t)(k0 + y + i) * N + n0 + x];
    __syncthreads();
    #pragma unroll
    for (int i = 0; i < 32; i += 8) {
        float v = t[x][y + i];
        __nv_bfloat16 h = __float2bfloat16(v);
        __nv_bfloat16 l = __float2bfloat16(v - __bfloat162float(h));
        size_t base = (size_t)(n0 + y + i) * KCAT + k0 + x;
        T[base]          = h;
        T[base + DIM]    = l;
        T[base + 2*DIM]  = h;
    }
}

// ===========================================================================
// mma.sync bf16 GEMM (unchanged from round 6, passing at tensor=82%).
// ===========================================================================
#define G_BK      32
#define G_STAGES  4
#define G_STAGE_B 16384
#define G_SMEM    (G_STAGES * G_STAGE_B)

__device__ __forceinline__ uint32_t sw_off(int r, int c) {
    return (uint32_t)(((r << 2) | (c ^ ((r >> 1) & 3))) << 4);
}

__global__ __launch_bounds__(128, 2) void gemm_mma(
    const __nv_bfloat16* __restrict__ A, const __nv_bfloat16* __restrict__ Bm,
    const float* __restrict__ bias, float* __restrict__ C, int N, int K)
{
    extern __shared__ char smraw[];
    const uint32_t sbase = smem_u32(smraw);

    const int tid = threadIdx.x, lane = tid & 31, wid = tid >> 5;
    const int row0 = blockIdx.x * 128;
    const int col0 = blockIdx.y * 128;
    const int mw = (wid >> 1) * 64;
    const int nw = (wid & 1) * 64;
    const int sub = lane >> 3, l7 = lane & 7;

    float acc[4][8][4];
    #pragma unroll
    for (int i = 0; i < 4; i++)
        #pragma unroll
        for (int j = 0; j < 8; j++)
            #pragma unroll
            for (int q = 0; q < 4; q++) acc[i][j][q] = 0.f;

    const int NIT = K / G_BK;

    auto load_stage = [&](int st, int k0) {
        const uint32_t sA = sbase + st * G_STAGE_B;
        const uint32_t sB = sA + 8192;
        #pragma unroll
        for (int i = 0; i < 4; i++) {
            int f = tid + i * 128;
            int r = f >> 2, c = f & 3;
            uint32_t so = sw_off(r, c);
            cp16(sA + so, A  + (size_t)(row0 + r) * K + k0 + c * 8);
            cp16(sB + so, Bm + (size_t)(col0 + r) * K + k0 + c * 8);
        }
    };

    #pragma unroll
    for (int s = 0; s < G_STAGES - 1; s++) { load_stage(s, s * G_BK); CP_COMMIT(); }

    #pragma unroll 1
    for (int it = 0; it < NIT; it++) {
        CP_WAIT2();
        __syncthreads();
        const uint32_t uA = sbase + (it & 3) * G_STAGE_B;
        const uint32_t uB = uA + 8192;

        #pragma unroll
        for (int kk = 0; kk < 2; kk++) {
            const int c0 = kk * 2;
            uint32_t a[4][4], b[4][4];
            #pragma unroll
            for (int i = 0; i < 4; i++) {
                int r = mw + i * 16 + ((sub & 1) << 3) + l7;
                int c = c0 + (sub >> 1);
                ldm_x4(a[i], uA + sw_off(r, c));
            }
            #pragma unroll
            for (int p = 0; p < 4; p++) {
                int r = nw + p * 16 + ((sub >> 1) << 3) + l7;
                int c = c0 + (sub & 1);
                ldm_x4(b[p], uB + sw_off(r, c));
            }
            #pragma unroll
            for (int i = 0; i < 4; i++)
                #pragma unroll
                for (int j = 0; j < 8; j++)
                    mma_bf16(acc[i][j], a[i], &b[j >> 1][(j & 1) * 2]);
        }

        const int nld = it + G_STAGES - 1;
        if (nld < NIT) load_stage(nld & 3, nld * G_BK);
        CP_COMMIT();
    }

    const int g = lane >> 2, tq = lane & 3;
    #pragma unroll
    for (int i = 0; i < 4; i++) {
        int r = row0 + mw + i * 16 + g;
        #pragma unroll
        for (int j = 0; j < 8; j++) {
            int c = col0 + nw + j * 8 + tq * 2;
            float bx = bias[c], by = bias[c + 1];
            float2 o0; o0.x = acc[i][j][0] + bx; o0.y = acc[i][j][1] + by;
            float2 o1; o1.x = acc[i][j][2] + bx; o1.y = acc[i][j][3] + by;
            *(float2*)(C + (size_t)r * N + c)       = o0;
            *(float2*)(C + (size_t)(r + 8) * N + c) = o1;
        }
    }
}

// ===========================================================================
// Fused RMSNorm + RoPE -> bf16 hi/lo concat q/k per head; v -> fp16.
// grid (S, 3): y=0 q, y=1 k, y=2 v-convert. 256 threads.
// ===========================================================================
__global__ __launch_bounds__(256) void normrope_kernel(
    const float* __restrict__ qkv,
    const float* __restrict__ w_qn, const float* __restrict__ w_kn,
    const float* __restrict__ cosf, const float* __restrict__ sinf,
    __nv_bfloat16* __restrict__ qH, __nv_bfloat16* __restrict__ kH,
    __half* __restrict__ vH)
{
    const int s   = blockIdx.x;
    const int sel = blockIdx.y;
    const int tid = threadIdx.x;

    if (sel == 2) {   // v: fp32 -> fp16 copy
        const float* vrow = qkv + (size_t)s * QKVW + 2 * DIM;
        __half* vout = vH + (size_t)s * DIM;
        for (int i = tid; i < DIM / 2; i += 256) {
            float2 v = ((const float2*)vrow)[i];
            ((__half2*)vout)[i] = __floats2half2_rn(v.x, v.y);
        }
        return;
    }

    const float* row = qkv + (size_t)s * QKVW + sel * DIM;
    const float* w = sel ? w_kn : w_qn;
    __nv_bfloat16* dst = sel ? kH : qH;

    const int lane = tid & 31, wid = tid >> 5;
    __shared__ float red[8];
    __shared__ float s_rstd;

    float ss = 0.f;
    const float4* row4 = (const float4*)row;
    for (int i = tid; i < DIM / 4; i += 256) {
        float4 v = row4[i];
        ss += v.x * v.x + v.y * v.y + v.z * v.z + v.w * v.w;
    }
    #pragma unroll
    for (int o = 16; o; o >>= 1) ss += __shfl_xor_sync(0xffffffffu, ss, o);
    if (lane == 0) red[wid] = ss;
    __syncthreads();
    if (tid == 0) {
        float t = 0.f;
        #pragma unroll
        for (int i = 0; i < 8; i++) t += red[i];
        s_rstd = rsqrtf(t / (float)DIM + EPS);
    }
    __syncthreads();
    const float rstd = s_rstd;

    const float* crow = cosf + (size_t)s * HDIM;
    const float* srow = sinf + (size_t)s * HDIM;
    for (int p = tid; p < DIM / 2; p += 256) {
        int head = p >> 6;
        int t    = p & 63;
        int e0 = head * HDIM + 2 * t;
        float xe = row[e0]     * rstd * w[e0];
        float xo = row[e0 + 1] * rstd * w[e0 + 1];
        float c  = crow[2 * t];
        float sn = srow[2 * t + 1];
        float oe = xe * c - xo * sn;
        float oo = xe * sn + xo * c;

        __nv_bfloat16 he = __float2bfloat16(oe);
        __nv_bfloat16 ho = __float2bfloat16(oo);
        __nv_bfloat162 hp; hp.x = he; hp.y = ho;
        __nv_bfloat162 lp;
        lp.x = __float2bfloat16(oe - __bfloat162float(he));
        lp.y = __float2bfloat16(oo - __bfloat162float(ho));

        __nv_bfloat16* out = dst + ((size_t)s * NHEAD + head) * 384 + 2 * t;
        if (sel == 0) {   // q: [hi | hi | lo]
            *(__nv_bfloat162*)(out)       = hp;
            *(__nv_bfloat162*)(out + 128) = hp;
            *(__nv_bfloat162*)(out + 256) = lp;
        } else {          // k: [hi | lo | hi]
            *(__nv_bfloat162*)(out)       = hp;
            *(__nv_bfloat162*)(out + 128) = lp;
            *(__nv_bfloat162*)(out + 256) = hp;
        }
    }
}

// ===========================================================================
// Tensorized flash attention.
//   Br=64 (4 warps x m16), Bc=64, QK^T: bf16 k=384 concat; PV: fp16 k=64.
//   K/V double-buffered cp.async; softmax in registers; writes attC concat.
//   Rows padded to 16B-odd chunk counts -> conflict-free ldmatrix.
// ===========================================================================
#define FB_BC   64
#define FB_NT   (S_LEN / FB_BC)    // 32
#define QK_CH   48                 // 16B chunks per q/k row (384 bf16)
#define QROWB   784                // 49 chunks (pad 1)
#define VROWB   272                // 17 chunks (pad 1)
#define FB_QS   0
#define FB_KS(st) (50176 + (st) * 50176)
#define FB_VS(st) (150528 + (st) * 17408)
#define FB_SMEM 185344

__global__ __launch_bounds__(128, 1) void fa_mma(
    const __nv_bfloat16* __restrict__ qH, const __nv_bfloat16* __restrict__ kH,
    const __half* __restrict__ vH, __nv_bfloat16* __restrict__ attC)
{
    extern __shared__ char smraw[];
    const uint32_t sb = smem_u32(smraw);
    const int tid = threadIdx.x, lane = tid & 31, w = tid >> 5;
    const int sub = lane >> 3, l7 = lane & 7;
    const int q0 = blockIdx.x * 64, h = blockIdx.y;
    const int mw = w * 16;

    // ---- Q tile load (grouped with tile 0) ----
    #pragma unroll
    for (int i = 0; i < 24; i++) {
        int f = tid + i * 128, r = f / QK_CH, c = f % QK_CH;
        cp16(sb + FB_QS + r * QROWB + c * 16,
             qH + ((size_t)(q0 + r) * NHEAD + h) * 384 + c * 8);
    }
    auto load_kv = [&](int st, int kt) {
        const int kb = kt * FB_BC;
        #pragma unroll
        for (int i = 0; i < 24; i++) {
            int f = tid + i * 128, r = f / QK_CH, c = f % QK_CH;
            cp16(sb + FB_KS(st) + r * QROWB + c * 16,
                 kH + ((size_t)(kb + r) * NHEAD + h) * 384 + c * 8);
        }
        #pragma unroll
        for (int i = 0; i < 8; i++) {
            int f = tid + i * 128, r = f >> 4, c = f & 15;
            cp16(sb + FB_VS(st) + r * VROWB + c * 16,
                 vH + ((size_t)(kb + r) * NHEAD + h) * 128 + c * 8);
        }
    };
    load_kv(0, 0); CP_COMMIT();
    load_kv(1, 1); CP_COMMIT();

    float m0 = -1e30f, m1 = -1e30f, l0 = 0.f, l1 = 0.f;
    float oacc[16][4];
    #pragma unroll
    for (int i = 0; i < 16; i++)
        #pragma unroll
        for (int j = 0; j < 4; j++) oacc[i][j] = 0.f;

    #pragma unroll 1
    for (int kt = 0; kt < FB_NT; kt++) {
        CP_WAIT1();
        __syncthreads();
        const uint32_t Qs = sb + FB_QS;
        const uint32_t Ks = sb + FB_KS(kt & 1);
        const uint32_t Vs = sb + FB_VS(kt & 1);

        // ---- S = Q K^T (bf16x3 concat, k'=384) ----
        float s[8][4];
        #pragma unroll
        for (int j = 0; j < 8; j++)
            #pragma unroll
            for (int q = 0; q < 4; q++) s[j][q] = 0.f;

        #pragma unroll 4
        for (int ks = 0; ks < 24; ks++) {
            uint32_t af[4];
            ldm_x4(af, Qs + (mw + ((sub & 1) << 3) + l7) * QROWB
                          + (2 * ks + (sub >> 1)) * 16);
            #pragma unroll
            for (int p = 0; p < 4; p++) {
                uint32_t bf[4];
                ldm_x4(bf, Ks + (p * 16 + ((sub >> 1) << 3) + l7) * QROWB
                              + (2 * ks + (sub & 1)) * 16);
                mma_bf16(s[2 * p],     af, bf);
                mma_bf16(s[2 * p + 1], af, bf + 2);
            }
        }

        // ---- register softmax (rows r0 = mw + lane/4, r1 = r0+8) ----
        float rmx0 = -1e30f, rmx1 = -1e30f;
        #pragma unroll
        for (int j = 0; j < 8; j++) {
            s[j][0] *= ATT_SCALE; s[j][1] *= ATT_SCALE;
            s[j][2] *= ATT_SCALE; s[j][3] *= ATT_SCALE;
            rmx0 = fmaxf(rmx0, fmaxf(s[j][0], s[j][1]));
            rmx1 = fmaxf(rmx1, fmaxf(s[j][2], s[j][3]));
        }
        rmx0 = fmaxf(rmx0, __shfl_xor_sync(0xffffffffu, rmx0, 1));
        rmx0 = fmaxf(rmx0, __shfl_xor_sync(0xffffffffu, rmx0, 2));
        rmx1 = fmaxf(rmx1, __shfl_xor_sync(0xffffffffu, rmx1, 1));
        rmx1 = fmaxf(rmx1, __shfl_xor_sync(0xffffffffu, rmx1, 2));

        float nm0 = fmaxf(m0, rmx0), nm1 = fmaxf(m1, rmx1);
        float a0 = __expf(m0 - nm0), a1 = __expf(m1 - nm1);
        m0 = nm0; m1 = nm1;

        float ls0 = 0.f, ls1 = 0.f;
        #pragma unroll
        for (int j = 0; j < 8; j++) {
            s[j][0] = __expf(s[j][0] - nm0);
            s[j][1] = __expf(s[j][1] - nm0);
            s[j][2] = __expf(s[j][2] - nm1);
            s[j][3] = __expf(s[j][3] - nm1);
            ls0 += s[j][0] + s[j][1];
            ls1 += s[j][2] + s[j][3];
        }
        ls0 += __shfl_xor_sync(0xffffffffu, ls0, 1);
        ls0 += __shfl_xor_sync(0xffffffffu, ls0, 2);
        ls1 += __shfl_xor_sync(0xffffffffu, ls1, 1);
        ls1 += __shfl_xor_sync(0xffffffffu, ls1, 2);
        l0 = l0 * a0 + ls0;
        l1 = l1 * a1 + ls1;

        #pragma unroll
        for (int nb = 0; nb < 16; nb++) {
            oacc[nb][0] *= a0; oacc[nb][1] *= a0;
            oacc[nb][2] *= a1; oacc[nb][3] *= a1;
        }

        // ---- O += P @ V (fp16, P frags from registers, V via ldmatrix.trans)
        #pragma unroll
        for (int kb = 0; kb < 4; kb++) {
            uint32_t a[4];
            a[0] = f22h2(s[2 * kb][0],     s[2 * kb][1]);
            a[1] = f22h2(s[2 * kb][2],     s[2 * kb][3]);
            a[2] = f22h2(s[2 * kb + 1][0], s[2 * kb + 1][1]);
            a[3] = f22h2(s[2 * kb + 1][2], s[2 * kb + 1][3]);
            #pragma unroll
            for (int nb = 0; nb < 16; nb += 2) {
                uint32_t bf[4];
                ldm_x4t(bf, Vs + (kb * 16 + ((sub & 1) << 3) + l7) * VROWB
                               + (nb * 8 + ((sub >> 1) << 3)) * 2);
                mma_f16(oacc[nb],     a, bf);
                mma_f16(oacc[nb + 1], a, bf + 2);
            }
        }

        __syncthreads();
        if (kt + 2 < FB_NT) load_kv(kt & 1, kt + 2);
        CP_COMMIT();
    }

    // ---- epilogue: O/l -> attC concat [hi | hi | lo] ----
    const int g = lane >> 2, tq = lane & 3;
    const float inv0 = 1.f / l0, inv1 = 1.f / l1;
    __nv_bfloat16* r0p = attC + (size_t)(q0 + mw + g) * KCAT;
    __nv_bfloat16* r1p = attC + (size_t)(q0 + mw + g + 8) * KCAT;
    #pragma unroll
    for (int nb = 0; nb < 16; nb++) {
        int c = h * HDIM + nb * 8 + tq * 2;
        float x0 = oacc[nb][0] * inv0, y0 = oacc[nb][1] * inv0;
        float x1 = oacc[nb][2] * inv1, y1 = oacc[nb][3] * inv1;

        __nv_bfloat16 hx0 = __float2bfloat16(x0), hy0 = __float2bfloat16(y0);
        __nv_bfloat162 hp0; hp0.x = hx0; hp0.y = hy0;
        __nv_bfloat162 lp0;
        lp0.x = __float2bfloat16(x0 - __bfloat162float(hx0));
        lp0.y = __float2bfloat16(y0 - __bfloat162float(hy0));
        *(__nv_bfloat162*)(r0p + c)           = hp0;
        *(__nv_bfloat162*)(r0p + DIM + c)     = hp0;
        *(__nv_bfloat162*)(r0p + 2 * DIM + c) = lp0;

        __nv_bfloat16 hx1 = __float2bfloat16(x1), hy1 = __float2bfloat16(y1);
        __nv_bfloat162 hp1; hp1.x = hx1; hp1.y = hy1;
        __nv_bfloat162 lp1;
        lp1.x = __float2bfloat16(x1 - __bfloat162float(hx1));
        lp1.y = __float2bfloat16(y1 - __bfloat162float(hy1));
        *(__nv_bfloat162*)(r1p + c)           = hp1;
        *(__nv_bfloat162*)(r1p + DIM + c)     = hp1;
        *(__nv_bfloat162*)(r1p + 2 * DIM + c) = lp1;
    }
}

// ===========================================================================
// kernel_launch
// ===========================================================================
extern "C" void kernel_launch(void* const* d_in, const int* in_sizes, int n_in,
                              void* d_out, int out_size)
{
    const float* hs     = (const float*)d_in[0];
    const float* cosf_  = (const float*)d_in[1];
    const float* sinf_  = (const float*)d_in[2];
    const float* w_qkv  = (const float*)d_in[3];
    const float* b_qkv  = (const float*)d_in[4];
    const float* w_qn   = (const float*)d_in[5];
    const float* w_kn   = (const float*)d_in[6];
    const float* w_out  = (const float*)d_in[7];
    const float* b_out  = (const float*)d_in[8];
    float* out = (float*)d_out;

    float* qkv;
    __nv_bfloat16 *hsC, *attC, *wqkvC, *woutC, *qH, *kH;
    __half* vH;
    cudaGetSymbolAddress((void**)&qkv,   g_qkv);
    cudaGetSymbolAddress((void**)&hsC,   g_hsC);
    cudaGetSymbolAddress((void**)&attC,  g_attC);
    cudaGetSymbolAddress((void**)&wqkvC, g_wqkvC);
    cudaGetSymbolAddress((void**)&woutC, g_woutC);
    cudaGetSymbolAddress((void**)&qH,    g_qH);
    cudaGetSymbolAddress((void**)&kH,    g_kH);
    cudaGetSymbolAddress((void**)&vH,    g_vH);

    cudaFuncSetAttribute(gemm_mma,
                         cudaFuncAttributeMaxDynamicSharedMemorySize, G_SMEM);
    cudaFuncSetAttribute(fa_mma,
                         cudaFuncAttributeMaxDynamicSharedMemorySize, FB_SMEM);

    // --- pre-passes ---
    transpose_cat<<<dim3(QKVW/32, DIM/32), dim3(32,8)>>>(w_qkv, wqkvC, QKVW);
    transpose_cat<<<dim3(DIM/32,  DIM/32), dim3(32,8)>>>(w_out, woutC, DIM);
    convert_cat<<<2048, 256>>>(hs, hsC, S_LEN);

    // --- qkv = hs @ w_qkv + b ---
    gemm_mma<<<dim3(S_LEN/128, QKVW/128), 128, G_SMEM>>>(
        hsC, wqkvC, b_qkv, qkv, QKVW, KCAT);

    // --- rmsnorm + rope -> bf16 q/k concat, fp16 v ---
    normrope_kernel<<<dim3(S_LEN, 3), 256>>>(qkv, w_qn, w_kn, cosf_, sinf_,
                                             qH, kH, vH);

    // --- tensorized flash attention -> attC (bf16 concat) ---
    fa_mma<<<dim3(S_LEN/64, NHEAD), 128, FB_SMEM>>>(qH, kH, vH, attC);

    // --- out = att @ w_out + b ---
    gemm_mma<<<dim3(S_LEN/128, DIM/128), 128, G_SMEM>>>(
        attC, woutC, b_out, out, DIM, KCAT);
}

// round 8
// speedup vs baseline: 3.7912x; 1.0592x over previous
#include <cuda_runtime.h>
#include <cuda_bf16.h>
#include <cuda_fp16.h>
#include <cstdint>
#include <math.h>

// ---------------------------------------------------------------------------
// StaticSelfAttention: B=1, S=2048, DIM=5120, H=40, D=128, fp32.
// Round 8: FA v3 (Q-in-registers, deduped hi/lo smem, 2 CTAs/SM),
//          v produced fp16 directly in GEMM1 epilogue.
// ---------------------------------------------------------------------------

#define S_LEN 2048
#define DIM   5120
#define NHEAD 40
#define HDIM  128
#define QKVW  (3*DIM)          // 15360
#define KCAT  (3*DIM)          // concat K' = 15360
#define EPS   1e-6f
#define ATT_SCALE 0.08838834764831845f   // 128^-0.5

// -------------------- scratch (__device__ globals; no allocs) --------------
__device__ float g_qkv[(size_t)S_LEN * QKVW];
__device__ __nv_bfloat16 g_hsC [(size_t)S_LEN * KCAT];    // [hi | hi | lo]
__device__ __nv_bfloat16 g_attC[(size_t)S_LEN * KCAT];    // [hi | hi | lo]
__device__ __nv_bfloat16 g_wqkvC[(size_t)QKVW * KCAT];    // [N][ hi | lo | hi ]
__device__ __nv_bfloat16 g_woutC[(size_t)DIM  * KCAT];
__device__ __nv_bfloat16 g_qH[(size_t)S_LEN * NHEAD * 256];  // [s][h][hi|lo]
__device__ __nv_bfloat16 g_kH[(size_t)S_LEN * NHEAD * 256];  // [s][h][hi|lo]
__device__ __half        g_vH[(size_t)S_LEN * DIM];          // [s][h*128+d]

// -------------------- PTX helpers (baseline ISA only) ----------------------
__device__ __forceinline__ uint32_t smem_u32(const void* p) {
    uint32_t a;
    asm("{ .reg .u64 t; cvta.to.shared.u64 t, %1; cvt.u32.u64 %0, t; }"
        : "=r"(a) : "l"(p));
    return a;
}
__device__ __forceinline__ void cp16(uint32_t dst, const void* src) {
    asm volatile("cp.async.cg.shared.global [%0], [%1], 16;\n"
                 :: "r"(dst), "l"(src));
}
#define CP_COMMIT() asm volatile("cp.async.commit_group;\n" ::: "memory")
#define CP_WAIT2()  asm volatile("cp.async.wait_group 2;\n" ::: "memory")
#define CP_WAIT1()  asm volatile("cp.async.wait_group 1;\n" ::: "memory")
#define CP_WAIT0()  asm volatile("cp.async.wait_group 0;\n" ::: "memory")

__device__ __forceinline__ void ldm_x4(uint32_t* r, uint32_t a) {
    asm volatile("ldmatrix.sync.aligned.m8n8.x4.shared.b16 {%0,%1,%2,%3}, [%4];\n"
                 : "=r"(r[0]), "=r"(r[1]), "=r"(r[2]), "=r"(r[3]) : "r"(a));
}
__device__ __forceinline__ void ldm_x4t(uint32_t* r, uint32_t a) {
    asm volatile("ldmatrix.sync.aligned.m8n8.x4.trans.shared.b16 {%0,%1,%2,%3}, [%4];\n"
                 : "=r"(r[0]), "=r"(r[1]), "=r"(r[2]), "=r"(r[3]) : "r"(a));
}
__device__ __forceinline__ void mma_bf16(float* d, const uint32_t* a,
                                         const uint32_t* b) {
    asm volatile(
        "mma.sync.aligned.m16n8k16.row.col.f32.bf16.bf16.f32 "
        "{%0,%1,%2,%3}, {%4,%5,%6,%7}, {%8,%9}, {%0,%1,%2,%3};\n"
        : "+f"(d[0]), "+f"(d[1]), "+f"(d[2]), "+f"(d[3])
        : "r"(a[0]), "r"(a[1]), "r"(a[2]), "r"(a[3]), "r"(b[0]), "r"(b[1]));
}
__device__ __forceinline__ void mma_f16(float* d, const uint32_t* a,
                                        const uint32_t* b) {
    asm volatile(
        "mma.sync.aligned.m16n8k16.row.col.f32.f16.f16.f32 "
        "{%0,%1,%2,%3}, {%4,%5,%6,%7}, {%8,%9}, {%0,%1,%2,%3};\n"
        : "+f"(d[0]), "+f"(d[1]), "+f"(d[2]), "+f"(d[3])
        : "r"(a[0]), "r"(a[1]), "r"(a[2]), "r"(a[3]), "r"(b[0]), "r"(b[1]));
}
__device__ __forceinline__ uint32_t f22h2(float x, float y) {
    __half2 t = __floats2half2_rn(x, y);
    return *reinterpret_cast<uint32_t*>(&t);
}

// ===========================================================================
// Pre-pass 1: fp32 [M][DIM] -> bf16 concat [M][KCAT] = [hi | hi | lo]
// ===========================================================================
__global__ __launch_bounds__(256) void convert_cat(
    const float* __restrict__ X, __nv_bfloat16* __restrict__ Y, int M)
{
    const int total = M * (DIM / 4);
    for (int i = blockIdx.x * 256 + threadIdx.x; i < total;
         i += gridDim.x * 256) {
        int row = i / (DIM / 4);
        int c4  = (i % (DIM / 4)) * 4;
        float4 v = ((const float4*)X)[i];
        __nv_bfloat16 h0 = __float2bfloat16(v.x);
        __nv_bfloat16 h1 = __float2bfloat16(v.y);
        __nv_bfloat16 h2 = __float2bfloat16(v.z);
        __nv_bfloat16 h3 = __float2bfloat16(v.w);
        __nv_bfloat162 hp0; hp0.x = h0; hp0.y = h1;
        __nv_bfloat162 hp1; hp1.x = h2; hp1.y = h3;
        __nv_bfloat162 lp0, lp1;
        lp0.x = __float2bfloat16(v.x - __bfloat162float(h0));
        lp0.y = __float2bfloat16(v.y - __bfloat162float(h1));
        lp1.x = __float2bfloat16(v.z - __bfloat162float(h2));
        lp1.y = __float2bfloat16(v.w - __bfloat162float(h3));
        __nv_bfloat16* yr = Y + (size_t)row * KCAT;
        *(__nv_bfloat162*)(yr + c4)     = hp0;
        *(__nv_bfloat162*)(yr + c4 + 2) = hp1;
        *(__nv_bfloat162*)(yr + DIM + c4)     = hp0;
        *(__nv_bfloat162*)(yr + DIM + c4 + 2) = hp1;
        *(__nv_bfloat162*)(yr + 2*DIM + c4)     = lp0;
        *(__nv_bfloat162*)(yr + 2*DIM + c4 + 2) = lp1;
    }
}

// ===========================================================================
// Pre-pass 2: W[K=DIM][N] fp32 -> T[N][KCAT] bf16 = [hi | lo | hi]
// ===========================================================================
__global__ void transpose_cat(const float* __restrict__ W,
                              __nv_bfloat16* __restrict__ T, int N)
{
    __shared__ float t[32][33];
    const int n0 = blockIdx.x * 32, k0 = blockIdx.y * 32;
    const int x = threadIdx.x, y = threadIdx.y;   // 32 x 8
    #pragma unroll
    for (int i = 0; i < 32; i += 8)
        t[y + i][x] = W[(size_t)(k0 + y + i) * N + n0 + x];
    __syncthreads();
    #pragma unroll
    for (int i = 0; i < 32; i += 8) {
        float v = t[x][y + i];
        __nv_bfloat16 h = __float2bfloat16(v);
        __nv_bfloat16 l = __float2bfloat16(v - __bfloat162float(h));
        size_t base = (size_t)(n0 + y + i) * KCAT + k0 + x;
        T[base]          = h;
        T[base + DIM]    = l;
        T[base + 2*DIM]  = h;
    }
}

// ===========================================================================
// mma.sync bf16 GEMM (mainloop unchanged; epilogue optionally emits fp16 v).
// ===========================================================================
#define G_BK      32
#define G_STAGES  4
#define G_STAGE_B 16384
#define G_SMEM    (G_STAGES * G_STAGE_B)

__device__ __forceinline__ uint32_t sw_off(int r, int c) {
    return (uint32_t)(((r << 2) | (c ^ ((r >> 1) & 3))) << 4);
}

__global__ __launch_bounds__(128, 2) void gemm_mma(
    const __nv_bfloat16* __restrict__ A, const __nv_bfloat16* __restrict__ Bm,
    const float* __restrict__ bias, float* __restrict__ C,
    __half* __restrict__ vout, int N, int K)
{
    extern __shared__ char smraw[];
    const uint32_t sbase = smem_u32(smraw);

    const int tid = threadIdx.x, lane = tid & 31, wid = tid >> 5;
    const int row0 = blockIdx.x * 128;
    const int col0 = blockIdx.y * 128;
    const int mw = (wid >> 1) * 64;
    const int nw = (wid & 1) * 64;
    const int sub = lane >> 3, l7 = lane & 7;

    float acc[4][8][4];
    #pragma unroll
    for (int i = 0; i < 4; i++)
        #pragma unroll
        for (int j = 0; j < 8; j++)
            #pragma unroll
            for (int q = 0; q < 4; q++) acc[i][j][q] = 0.f;

    const int NIT = K / G_BK;

    auto load_stage = [&](int st, int k0) {
        const uint32_t sA = sbase + st * G_STAGE_B;
        const uint32_t sB = sA + 8192;
        #pragma unroll
        for (int i = 0; i < 4; i++) {
            int f = tid + i * 128;
            int r = f >> 2, c = f & 3;
            uint32_t so = sw_off(r, c);
            cp16(sA + so, A  + (size_t)(row0 + r) * K + k0 + c * 8);
            cp16(sB + so, Bm + (size_t)(col0 + r) * K + k0 + c * 8);
        }
    };

    #pragma unroll
    for (int s = 0; s < G_STAGES - 1; s++) { load_stage(s, s * G_BK); CP_COMMIT(); }

    #pragma unroll 1
    for (int it = 0; it < NIT; it++) {
        CP_WAIT2();
        __syncthreads();
        const uint32_t uA = sbase + (it & 3) * G_STAGE_B;
        const uint32_t uB = uA + 8192;

        #pragma unroll
        for (int kk = 0; kk < 2; kk++) {
            const int c0 = kk * 2;
            uint32_t a[4][4], b[4][4];
            #pragma unroll
            for (int i = 0; i < 4; i++) {
                int r = mw + i * 16 + ((sub & 1) << 3) + l7;
                int c = c0 + (sub >> 1);
                ldm_x4(a[i], uA + sw_off(r, c));
            }
            #pragma unroll
            for (int p = 0; p < 4; p++) {
                int r = nw + p * 16 + ((sub >> 1) << 3) + l7;
                int c = c0 + (sub & 1);
                ldm_x4(b[p], uB + sw_off(r, c));
            }
            #pragma unroll
            for (int i = 0; i < 4; i++)
                #pragma unroll
                for (int j = 0; j < 8; j++)
                    mma_bf16(acc[i][j], a[i], &b[j >> 1][(j & 1) * 2]);
        }

        const int nld = it + G_STAGES - 1;
        if (nld < NIT) load_stage(nld & 3, nld * G_BK);
        CP_COMMIT();
    }

    const int g = lane >> 2, tq = lane & 3;
    const bool vtile = (vout != nullptr) && (col0 >= 2 * DIM);
    #pragma unroll
    for (int i = 0; i < 4; i++) {
        int r = row0 + mw + i * 16 + g;
        #pragma unroll
        for (int j = 0; j < 8; j++) {
            int c = col0 + nw + j * 8 + tq * 2;
            float bx = bias[c], by = bias[c + 1];
            float x0 = acc[i][j][0] + bx, y0 = acc[i][j][1] + by;
            float x1 = acc[i][j][2] + bx, y1 = acc[i][j][3] + by;
            if (vtile) {
                int vc = c - 2 * DIM;
                __half2 h0 = __floats2half2_rn(x0, y0);
                __half2 h1 = __floats2half2_rn(x1, y1);
                *(__half2*)(vout + (size_t)r * DIM + vc)       = h0;
                *(__half2*)(vout + (size_t)(r + 8) * DIM + vc) = h1;
            } else {
                float2 o0; o0.x = x0; o0.y = y0;
                float2 o1; o1.x = x1; o1.y = y1;
                *(float2*)(C + (size_t)r * N + c)       = o0;
                *(float2*)(C + (size_t)(r + 8) * N + c) = o1;
            }
        }
    }
}

// ===========================================================================
// Fused RMSNorm + RoPE -> bf16 [hi|lo] (256 cols) per head for q and k.
// grid (S, 2): y=0 q, y=1 k. 256 threads.
// ===========================================================================
__global__ __launch_bounds__(256) void normrope_kernel(
    const float* __restrict__ qkv,
    const float* __restrict__ w_qn, const float* __restrict__ w_kn,
    const float* __restrict__ cosf, const float* __restrict__ sinf,
    __nv_bfloat16* __restrict__ qH, __nv_bfloat16* __restrict__ kH)
{
    const int s   = blockIdx.x;
    const int sel = blockIdx.y;
    const int tid = threadIdx.x;

    const float* row = qkv + (size_t)s * QKVW + sel * DIM;
    const float* w = sel ? w_kn : w_qn;
    __nv_bfloat16* dst = sel ? kH : qH;

    const int lane = tid & 31, wid = tid >> 5;
    __shared__ float red[8];
    __shared__ float s_rstd;

    float ss = 0.f;
    const float4* row4 = (const float4*)row;
    for (int i = tid; i < DIM / 4; i += 256) {
        float4 v = row4[i];
        ss += v.x * v.x + v.y * v.y + v.z * v.z + v.w * v.w;
    }
    #pragma unroll
    for (int o = 16; o; o >>= 1) ss += __shfl_xor_sync(0xffffffffu, ss, o);
    if (lane == 0) red[wid] = ss;
    __syncthreads();
    if (tid == 0) {
        float t = 0.f;
        #pragma unroll
        for (int i = 0; i < 8; i++) t += red[i];
        s_rstd = rsqrtf(t / (float)DIM + EPS);
    }
    __syncthreads();
    const float rstd = s_rstd;

    const float* crow = cosf + (size_t)s * HDIM;
    const float* srow = sinf + (size_t)s * HDIM;
    for (int p = tid; p < DIM / 2; p += 256) {
        int head = p >> 6;
        int t    = p & 63;
        int e0 = head * HDIM + 2 * t;
        float xe = row[e0]     * rstd * w[e0];
        float xo = row[e0 + 1] * rstd * w[e0 + 1];
        float c  = crow[2 * t];
        float sn = srow[2 * t + 1];
        float oe = xe * c - xo * sn;
        float oo = xe * sn + xo * c;

        __nv_bfloat16 he = __float2bfloat16(oe);
        __nv_bfloat16 ho = __float2bfloat16(oo);
        __nv_bfloat162 hp; hp.x = he; hp.y = ho;
        __nv_bfloat162 lp;
        lp.x = __float2bfloat16(oe - __bfloat162float(he));
        lp.y = __float2bfloat16(oo - __bfloat162float(ho));

        __nv_bfloat16* out = dst + ((size_t)s * NHEAD + head) * 256 + 2 * t;
        *(__nv_bfloat162*)(out)       = hp;   // hi at [0,128)
        *(__nv_bfloat162*)(out + 128) = lp;   // lo at [128,256)
    }
}

// ===========================================================================
// Tensorized flash attention v3.
//   Br=64 (4 warps), Bc=64. Q held in registers (hi/lo frags).
//   S = Qhi*Khi + Qhi*Klo + Qlo*Khi (3 segment passes, bf16).
//   PV fp16. K/V double-buffered cp.async. smem 100KB -> 2 CTAs/SM.
// ===========================================================================
#define FC_NT   (S_LEN / 64)       // 32
#define KROWB   528                // 33 x 16B chunks (32 data + 1 pad)
#define VROWB   272                // 17 x 16B chunks
#define FC_K(st) ((st) * 33792)
#define FC_V(st) (67584 + (st) * 17408)
#define FC_SMEM 102400

__global__ __launch_bounds__(128, 2) void fa_mma(
    const __nv_bfloat16* __restrict__ qH, const __nv_bfloat16* __restrict__ kH,
    const __half* __restrict__ vH, __nv_bfloat16* __restrict__ attC)
{
    extern __shared__ char smraw[];
    const uint32_t sb = smem_u32(smraw);
    const int tid = threadIdx.x, lane = tid & 31, w = tid >> 5;
    const int sub = lane >> 3, l7 = lane & 7;
    const int q0 = blockIdx.x * 64, h = blockIdx.y;
    const int mw = w * 16;

    // ---- stage Q tile through K0 buffer, then ldmatrix into registers ----
    #pragma unroll
    for (int i = 0; i < 16; i++) {
        int f = tid + i * 128, r = f >> 5, c = f & 31;
        cp16(sb + FC_K(0) + r * KROWB + c * 16,
             qH + ((size_t)(q0 + r) * NHEAD + h) * 256 + c * 8);
    }
    CP_COMMIT();
    CP_WAIT0();
    __syncthreads();

    uint32_t qhi[8][4], qlo[8][4];
    {
        const uint32_t qb = sb + FC_K(0)
                          + (mw + ((sub & 1) << 3) + l7) * KROWB;
        #pragma unroll
        for (int ks = 0; ks < 8; ks++) {
            ldm_x4(qhi[ks], qb + (2 * ks + (sub >> 1)) * 16);
            ldm_x4(qlo[ks], qb + (16 + 2 * ks + (sub >> 1)) * 16);
        }
    }
    __syncthreads();

    auto load_kv = [&](int st, int kt) {
        const int kb = kt * 64;
        #pragma unroll
        for (int i = 0; i < 16; i++) {
            int f = tid + i * 128, r = f >> 5, c = f & 31;
            cp16(sb + FC_K(st) + r * KROWB + c * 16,
                 kH + ((size_t)(kb + r) * NHEAD + h) * 256 + c * 8);
        }
        #pragma unroll
        for (int i = 0; i < 8; i++) {
            int f = tid + i * 128, r = f >> 4, c = f & 15;
            cp16(sb + FC_V(st) + r * VROWB + c * 16,
                 vH + (size_t)(kb + r) * DIM + h * HDIM + c * 8);
        }
    };
    load_kv(0, 0); CP_COMMIT();
    load_kv(1, 1); CP_COMMIT();

    float m0 = -1e30f, m1 = -1e30f, l0 = 0.f, l1 = 0.f;
    float oacc[16][4];
    #pragma unroll
    for (int i = 0; i < 16; i++)
        #pragma unroll
        for (int j = 0; j < 4; j++) oacc[i][j] = 0.f;

    #pragma unroll 1
    for (int kt = 0; kt < FC_NT; kt++) {
        CP_WAIT1();
        __syncthreads();
        const uint32_t Ks = sb + FC_K(kt & 1);
        const uint32_t Vs = sb + FC_V(kt & 1);
        const uint32_t kbase = Ks + (((sub >> 1) << 3) + l7) * KROWB;

        // ---- S = Qhi*Khi + Qhi*Klo + Qlo*Khi ----
        float s[8][4];
        #pragma unroll
        for (int j = 0; j < 8; j++)
            #pragma unroll
            for (int q = 0; q < 4; q++) s[j][q] = 0.f;

        #pragma unroll
        for (int seg = 0; seg < 3; seg++) {
            const int boff = (seg == 1) ? 16 : 0;
            #pragma unroll
            for (int ks = 0; ks < 8; ks++) {
                const uint32_t* af = (seg == 2) ? qlo[ks] : qhi[ks];
                const uint32_t ca = (boff + 2 * ks + (sub & 1)) * 16;
                #pragma unroll
                for (int p = 0; p < 4; p++) {
                    uint32_t bf[4];
                    ldm_x4(bf, kbase + p * 16 * KROWB + ca);
                    mma_bf16(s[2 * p],     af, bf);
                    mma_bf16(s[2 * p + 1], af, bf + 2);
                }
            }
        }

        // ---- register softmax ----
        float rmx0 = -1e30f, rmx1 = -1e30f;
        #pragma unroll
        for (int j = 0; j < 8; j++) {
            s[j][0] *= ATT_SCALE; s[j][1] *= ATT_SCALE;
            s[j][2] *= ATT_SCALE; s[j][3] *= ATT_SCALE;
            rmx0 = fmaxf(rmx0, fmaxf(s[j][0], s[j][1]));
            rmx1 = fmaxf(rmx1, fmaxf(s[j][2], s[j][3]));
        }
        rmx0 = fmaxf(rmx0, __shfl_xor_sync(0xffffffffu, rmx0, 1));
        rmx0 = fmaxf(rmx0, __shfl_xor_sync(0xffffffffu, rmx0, 2));
        rmx1 = fmaxf(rmx1, __shfl_xor_sync(0xffffffffu, rmx1, 1));
        rmx1 = fmaxf(rmx1, __shfl_xor_sync(0xffffffffu, rmx1, 2));

        float nm0 = fmaxf(m0, rmx0), nm1 = fmaxf(m1, rmx1);
        float a0 = __expf(m0 - nm0), a1 = __expf(m1 - nm1);
        m0 = nm0; m1 = nm1;

        float ls0 = 0.f, ls1 = 0.f;
        #pragma unroll
        for (int j = 0; j < 8; j++) {
            s[j][0] = __expf(s[j][0] - nm0);
            s[j][1] = __expf(s[j][1] - nm0);
            s[j][2] = __expf(s[j][2] - nm1);
            s[j][3] = __expf(s[j][3] - nm1);
            ls0 += s[j][0] + s[j][1];
            ls1 += s[j][2] + s[j][3];
        }
        ls0 += __shfl_xor_sync(0xffffffffu, ls0, 1);
        ls0 += __shfl_xor_sync(0xffffffffu, ls0, 2);
        ls1 += __shfl_xor_sync(0xffffffffu, ls1, 1);
        ls1 += __shfl_xor_sync(0xffffffffu, ls1, 2);
        l0 = l0 * a0 + ls0;
        l1 = l1 * a1 + ls1;

        #pragma unroll
        for (int nb = 0; nb < 16; nb++) {
            oacc[nb][0] *= a0; oacc[nb][1] *= a0;
            oacc[nb][2] *= a1; oacc[nb][3] *= a1;
        }

        // ---- O += P @ V (fp16) ----
        #pragma unroll
        for (int kb = 0; kb < 4; kb++) {
            uint32_t a[4];
            a[0] = f22h2(s[2 * kb][0],     s[2 * kb][1]);
            a[1] = f22h2(s[2 * kb][2],     s[2 * kb][3]);
            a[2] = f22h2(s[2 * kb + 1][0], s[2 * kb + 1][1]);
            a[3] = f22h2(s[2 * kb + 1][2], s[2 * kb + 1][3]);
            const uint32_t vb = Vs + (kb * 16 + ((sub & 1) << 3) + l7) * VROWB
                              + (((sub >> 1) << 3)) * 2;
            #pragma unroll
            for (int nb = 0; nb < 16; nb += 2) {
                uint32_t bf[4];
                ldm_x4t(bf, vb + nb * 16);
                mma_f16(oacc[nb],     a, bf);
                mma_f16(oacc[nb + 1], a, bf + 2);
            }
        }

        __syncthreads();
        if (kt + 2 < FC_NT) load_kv(kt & 1, kt + 2);
        CP_COMMIT();
    }

    // ---- epilogue: O/l -> attC concat [hi | hi | lo] ----
    const int g = lane >> 2, tq = lane & 3;
    const float inv0 = 1.f / l0, inv1 = 1.f / l1;
    __nv_bfloat16* r0p = attC + (size_t)(q0 + mw + g) * KCAT;
    __nv_bfloat16* r1p = attC + (size_t)(q0 + mw + g + 8) * KCAT;
    #pragma unroll
    for (int nb = 0; nb < 16; nb++) {
        int c = h * HDIM + nb * 8 + tq * 2;
        float x0 = oacc[nb][0] * inv0, y0 = oacc[nb][1] * inv0;
        float x1 = oacc[nb][2] * inv1, y1 = oacc[nb][3] * inv1;

        __nv_bfloat16 hx0 = __float2bfloat16(x0), hy0 = __float2bfloat16(y0);
        __nv_bfloat162 hp0; hp0.x = hx0; hp0.y = hy0;
        __nv_bfloat162 lp0;
        lp0.x = __float2bfloat16(x0 - __bfloat162float(hx0));
        lp0.y = __float2bfloat16(y0 - __bfloat162float(hy0));
        *(__nv_bfloat162*)(r0p + c)           = hp0;
        *(__nv_bfloat162*)(r0p + DIM + c)     = hp0;
        *(__nv_bfloat162*)(r0p + 2 * DIM + c) = lp0;

        __nv_bfloat16 hx1 = __float2bfloat16(x1), hy1 = __float2bfloat16(y1);
        __nv_bfloat162 hp1; hp1.x = hx1; hp1.y = hy1;
        __nv_bfloat162 lp1;
        lp1.x = __float2bfloat16(x1 - __bfloat162float(hx1));
        lp1.y = __float2bfloat16(y1 - __bfloat162float(hy1));
        *(__nv_bfloat162*)(r1p + c)           = hp1;
        *(__nv_bfloat162*)(r1p + DIM + c)     = hp1;
        *(__nv_bfloat162*)(r1p + 2 * DIM + c) = lp1;
    }
}

// ===========================================================================
// kernel_launch
// ===========================================================================
extern "C" void kernel_launch(void* const* d_in, const int* in_sizes, int n_in,
                              void* d_out, int out_size)
{
    const float* hs     = (const float*)d_in[0];
    const float* cosf_  = (const float*)d_in[1];
    const float* sinf_  = (const float*)d_in[2];
    const float* w_qkv  = (const float*)d_in[3];
    const float* b_qkv  = (const float*)d_in[4];
    const float* w_qn   = (const float*)d_in[5];
    const float* w_kn   = (const float*)d_in[6];
    const float* w_out  = (const float*)d_in[7];
    const float* b_out  = (const float*)d_in[8];
    float* out = (float*)d_out;

    float* qkv;
    __nv_bfloat16 *hsC, *attC, *wqkvC, *woutC, *qH, *kH;
    __half* vH;
    cudaGetSymbolAddress((void**)&qkv,   g_qkv);
    cudaGetSymbolAddress((void**)&hsC,   g_hsC);
    cudaGetSymbolAddress((void**)&attC,  g_attC);
    cudaGetSymbolAddress((void**)&wqkvC, g_wqkvC);
    cudaGetSymbolAddress((void**)&woutC, g_woutC);
    cudaGetSymbolAddress((void**)&qH,    g_qH);
    cudaGetSymbolAddress((void**)&kH,    g_kH);
    cudaGetSymbolAddress((void**)&vH,    g_vH);

    cudaFuncSetAttribute(gemm_mma,
                         cudaFuncAttributeMaxDynamicSharedMemorySize, G_SMEM);
    cudaFuncSetAttribute(fa_mma,
                         cudaFuncAttributeMaxDynamicSharedMemorySize, FC_SMEM);

    // --- pre-passes ---
    transpose_cat<<<dim3(QKVW/32, DIM/32), dim3(32,8)>>>(w_qkv, wqkvC, QKVW);
    transpose_cat<<<dim3(DIM/32,  DIM/32), dim3(32,8)>>>(w_out, woutC, DIM);
    convert_cat<<<2048, 256>>>(hs, hsC, S_LEN);

    // --- qkv = hs @ w_qkv + b  (v columns emitted fp16 to vH) ---
    gemm_mma<<<dim3(S_LEN/128, QKVW/128), 128, G_SMEM>>>(
        hsC, wqkvC, b_qkv, qkv, vH, QKVW, KCAT);

    // --- rmsnorm + rope -> bf16 [hi|lo] q/k ---
    normrope_kernel<<<dim3(S_LEN, 2), 256>>>(qkv, w_qn, w_kn, cosf_, sinf_,
                                             qH, kH);

    // --- tensorized flash attention -> attC (bf16 concat) ---
    fa_mma<<<dim3(S_LEN/64, NHEAD), 128, FC_SMEM>>>(qH, kH, vH, attC);

    // --- out = att @ w_out + b ---
    gemm_mma<<<dim3(S_LEN/128, DIM/128), 128, G_SMEM>>>(
        attC, woutC, b_out, out, nullptr, DIM, KCAT);
}

// round 9
// speedup vs baseline: 5.1155x; 1.3493x over previous
#include <cuda_runtime.h>
#include <cuda_bf16.h>
#include <cuda_fp16.h>
#include <cstdint>
#include <math.h>

// ---------------------------------------------------------------------------
// StaticSelfAttention: B=1, S=2048, DIM=5120, H=40, D=128, fp32.
// Round 9: single-pass TF32 GEMMs (pre-rounded operands, b16-ldmatrix trick),
//          FA unchanged (bf16x3 QK + fp16 PV), fp32 att handoff.
// ---------------------------------------------------------------------------

#define S_LEN 2048
#define DIM   5120
#define NHEAD 40
#define HDIM  128
#define QKVW  (3*DIM)          // 15360
#define EPS   1e-6f
#define ATT_SCALE 0.08838834764831845f   // 128^-0.5

// -------------------- scratch (__device__ globals; no allocs) --------------
__device__ float g_qkv[(size_t)S_LEN * QKVW];             // q,k fp32 (v -> vH)
__device__ float g_att[(size_t)S_LEN * DIM];              // FA out, tf32-valued
__device__ float g_hsR[(size_t)S_LEN * DIM];              // hs, tf32-rounded
__device__ float g_wqkvT[(size_t)QKVW * DIM];             // [N][K] tf32-valued
__device__ float g_woutT[(size_t)DIM  * DIM];             // [N][K] tf32-valued
__device__ __nv_bfloat16 g_qH[(size_t)S_LEN * NHEAD * 256];  // [s][h][hi|lo]
__device__ __nv_bfloat16 g_kH[(size_t)S_LEN * NHEAD * 256];  // [s][h][hi|lo]
__device__ __half        g_vH[(size_t)S_LEN * DIM];          // [s][h*128+d]

// -------------------- PTX helpers (baseline ISA only) ----------------------
__device__ __forceinline__ uint32_t smem_u32(const void* p) {
    uint32_t a;
    asm("{ .reg .u64 t; cvta.to.shared.u64 t, %1; cvt.u32.u64 %0, t; }"
        : "=r"(a) : "l"(p));
    return a;
}
__device__ __forceinline__ void cp16(uint32_t dst, const void* src) {
    asm volatile("cp.async.cg.shared.global [%0], [%1], 16;\n"
                 :: "r"(dst), "l"(src));
}
#define CP_COMMIT() asm volatile("cp.async.commit_group;\n" ::: "memory")
#define CP_WAIT1()  asm volatile("cp.async.wait_group 1;\n" ::: "memory")
#define CP_WAIT0()  asm volatile("cp.async.wait_group 0;\n" ::: "memory")

__device__ __forceinline__ void ldm_x4(uint32_t* r, uint32_t a) {
    asm volatile("ldmatrix.sync.aligned.m8n8.x4.shared.b16 {%0,%1,%2,%3}, [%4];\n"
                 : "=r"(r[0]), "=r"(r[1]), "=r"(r[2]), "=r"(r[3]) : "r"(a));
}
__device__ __forceinline__ void ldm_x4t(uint32_t* r, uint32_t a) {
    asm volatile("ldmatrix.sync.aligned.m8n8.x4.trans.shared.b16 {%0,%1,%2,%3}, [%4];\n"
                 : "=r"(r[0]), "=r"(r[1]), "=r"(r[2]), "=r"(r[3]) : "r"(a));
}
__device__ __forceinline__ void mma_bf16(float* d, const uint32_t* a,
                                         const uint32_t* b) {
    asm volatile(
        "mma.sync.aligned.m16n8k16.row.col.f32.bf16.bf16.f32 "
        "{%0,%1,%2,%3}, {%4,%5,%6,%7}, {%8,%9}, {%0,%1,%2,%3};\n"
        : "+f"(d[0]), "+f"(d[1]), "+f"(d[2]), "+f"(d[3])
        : "r"(a[0]), "r"(a[1]), "r"(a[2]), "r"(a[3]), "r"(b[0]), "r"(b[1]));
}
__device__ __forceinline__ void mma_f16(float* d, const uint32_t* a,
                                        const uint32_t* b) {
    asm volatile(
        "mma.sync.aligned.m16n8k16.row.col.f32.f16.f16.f32 "
        "{%0,%1,%2,%3}, {%4,%5,%6,%7}, {%8,%9}, {%0,%1,%2,%3};\n"
        : "+f"(d[0]), "+f"(d[1]), "+f"(d[2]), "+f"(d[3])
        : "r"(a[0]), "r"(a[1]), "r"(a[2]), "r"(a[3]), "r"(b[0]), "r"(b[1]));
}
__device__ __forceinline__ void mma_t32(float* d, const uint32_t* a,
                                        const uint32_t* b) {
    asm volatile(
        "mma.sync.aligned.m16n8k8.row.col.f32.tf32.tf32.f32 "
        "{%0,%1,%2,%3}, {%4,%5,%6,%7}, {%8,%9}, {%0,%1,%2,%3};\n"
        : "+f"(d[0]), "+f"(d[1]), "+f"(d[2]), "+f"(d[3])
        : "r"(a[0]), "r"(a[1]), "r"(a[2]), "r"(a[3]), "r"(b[0]), "r"(b[1]));
}
__device__ __forceinline__ uint32_t f22h2(float x, float y) {
    __half2 t = __floats2half2_rn(x, y);
    return *reinterpret_cast<uint32_t*>(&t);
}
__device__ __forceinline__ float rna(float x) {
    uint32_t u;
    asm("cvt.rna.tf32.f32 %0, %1;" : "=r"(u) : "f"(x));
    return __uint_as_float(u);
}

// ===========================================================================
// Pre-pass 1: elementwise tf32 RNA round, fp32 -> fp32(tf32-valued)
// ===========================================================================
__global__ __launch_bounds__(256) void round_t32(
    const float* __restrict__ X, float* __restrict__ Y, int n4)
{
    for (int i = blockIdx.x * 256 + threadIdx.x; i < n4;
         i += gridDim.x * 256) {
        float4 v = ((const float4*)X)[i];
        float4 o;
        o.x = rna(v.x); o.y = rna(v.y); o.z = rna(v.z); o.w = rna(v.w);
        ((float4*)Y)[i] = o;
    }
}

// ===========================================================================
// Pre-pass 2: W[K=DIM][N] fp32 -> T[N][K=DIM] fp32 (tf32 RNA-rounded)
// ===========================================================================
__global__ void transpose_t32(const float* __restrict__ W,
                              float* __restrict__ T, int N)
{
    __shared__ float t[32][33];
    const int n0 = blockIdx.x * 32, k0 = blockIdx.y * 32;
    const int x = threadIdx.x, y = threadIdx.y;   // 32 x 8
    #pragma unroll
    for (int i = 0; i < 32; i += 8)
        t[y + i][x] = W[(size_t)(k0 + y + i) * N + n0 + x];
    __syncthreads();
    #pragma unroll
    for (int i = 0; i < 32; i += 8)
        T[(size_t)(n0 + y + i) * DIM + k0 + x] = rna(t[x][y + i]);
}

// ===========================================================================
// TF32 GEMM: C[M,N] = A[M,K] @ Bm[N,K]^T + bias.
//   A, Bm fp32 tf32-valued. CTA 128x128, BK=32 floats, 3-stage cp.async.
//   4 warps, warp tile 64x64, m16n8k8 tf32 via b16-ldmatrix reinterpretation.
//   grid = (M/128, N/128); columns >= 2*DIM optionally emitted fp16 to vout.
// ===========================================================================
#define T_BK      32
#define T_STAGES  3
#define T_STAGE_B 32768                 // A 16KB + B 16KB
#define T_SMEM    (T_STAGES * T_STAGE_B)

__device__ __forceinline__ uint32_t tsw(int r, int c) {
    // 128B rows (8 x 16B chunks), XOR swizzle on chunk index
    return (uint32_t)(r * 128 + ((c ^ (r & 7)) << 4));
}

__global__ __launch_bounds__(128, 2) void gemm_t32(
    const float* __restrict__ A, const float* __restrict__ Bm,
    const float* __restrict__ bias, float* __restrict__ C,
    __half* __restrict__ vout, int N, int K)
{
    extern __shared__ char smraw[];
    const uint32_t sbase = smem_u32(smraw);

    const int tid = threadIdx.x, lane = tid & 31, wid = tid >> 5;
    const int row0 = blockIdx.x * 128;
    const int col0 = blockIdx.y * 128;
    const int mw = (wid >> 1) * 64;
    const int nw = (wid & 1) * 64;
    const int sub = lane >> 3, l7 = lane & 7;

    float acc[4][8][4];
    #pragma unroll
    for (int i = 0; i < 4; i++)
        #pragma unroll
        for (int j = 0; j < 8; j++)
            #pragma unroll
            for (int q = 0; q < 4; q++) acc[i][j][q] = 0.f;

    const int NIT = K / T_BK;

    auto load_stage = [&](int st, int k0) {
        const uint32_t sA = sbase + st * T_STAGE_B;
        const uint32_t sB = sA + 16384;
        #pragma unroll
        for (int i = 0; i < 8; i++) {
            int f = tid + i * 128;          // 0..1023
            int r = f >> 3, c = f & 7;
            uint32_t so = tsw(r, c);
            cp16(sA + so, A  + (size_t)(row0 + r) * K + k0 + c * 4);
            cp16(sB + so, Bm + (size_t)(col0 + r) * K + k0 + c * 4);
        }
    };

    load_stage(0, 0);       CP_COMMIT();
    load_stage(1, T_BK);    CP_COMMIT();

    #pragma unroll 1
    for (int it = 0; it < NIT; it++) {
        CP_WAIT1();
        __syncthreads();
        const uint32_t uA = sbase + (it % 3) * T_STAGE_B;
        const uint32_t uB = uA + 16384;

        #pragma unroll
        for (int kk = 0; kk < 4; kk++) {
            uint32_t a[4][4];
            #pragma unroll
            for (int i = 0; i < 4; i++) {
                int r = mw + i * 16 + ((sub & 1) << 3) + l7;
                int c = kk * 2 + (sub >> 1);
                ldm_x4(a[i], uA + tsw(r, c));
            }
            #pragma unroll
            for (int j = 0; j < 4; j++) {
                uint32_t b[4];
                int r = nw + j * 16 + ((sub >> 1) << 3) + l7;
                int c = kk * 2 + (sub & 1);
                ldm_x4(b, uB + tsw(r, c));
                #pragma unroll
                for (int i = 0; i < 4; i++) {
                    mma_t32(acc[i][2 * j],     a[i], b);
                    mma_t32(acc[i][2 * j + 1], a[i], b + 2);
                }
            }
        }

        const int nld = it + 2;
        if (nld < NIT) load_stage(nld % 3, nld * T_BK);
        CP_COMMIT();
    }

    const int g = lane >> 2, tq = lane & 3;
    const bool vtile = (vout != nullptr) && (col0 >= 2 * DIM);
    #pragma unroll
    for (int i = 0; i < 4; i++) {
        int r = row0 + mw + i * 16 + g;
        #pragma unroll
        for (int j = 0; j < 8; j++) {
            int c = col0 + nw + j * 8 + tq * 2;
            float bx = bias[c], by = bias[c + 1];
            float x0 = acc[i][j][0] + bx, y0 = acc[i][j][1] + by;
            float x1 = acc[i][j][2] + bx, y1 = acc[i][j][3] + by;
            if (vtile) {
                int vc = c - 2 * DIM;
                __half2 h0 = __floats2half2_rn(x0, y0);
                __half2 h1 = __floats2half2_rn(x1, y1);
                *(__half2*)(vout + (size_t)r * DIM + vc)       = h0;
                *(__half2*)(vout + (size_t)(r + 8) * DIM + vc) = h1;
            } else {
                float2 o0; o0.x = x0; o0.y = y0;
                float2 o1; o1.x = x1; o1.y = y1;
                *(float2*)(C + (size_t)r * N + c)       = o0;
                *(float2*)(C + (size_t)(r + 8) * N + c) = o1;
            }
        }
    }
}

// ===========================================================================
// Fused RMSNorm + RoPE -> bf16 [hi|lo] (256 cols) per head for q and k.
// ===========================================================================
__global__ __launch_bounds__(256) void normrope_kernel(
    const float* __restrict__ qkv,
    const float* __restrict__ w_qn, const float* __restrict__ w_kn,
    const float* __restrict__ cosf, const float* __restrict__ sinf,
    __nv_bfloat16* __restrict__ qH, __nv_bfloat16* __restrict__ kH)
{
    const int s   = blockIdx.x;
    const int sel = blockIdx.y;
    const int tid = threadIdx.x;

    const float* row = qkv + (size_t)s * QKVW + sel * DIM;
    const float* w = sel ? w_kn : w_qn;
    __nv_bfloat16* dst = sel ? kH : qH;

    const int lane = tid & 31, wid = tid >> 5;
    __shared__ float red[8];
    __shared__ float s_rstd;

    float ss = 0.f;
    const float4* row4 = (const float4*)row;
    for (int i = tid; i < DIM / 4; i += 256) {
        float4 v = row4[i];
        ss += v.x * v.x + v.y * v.y + v.z * v.z + v.w * v.w;
    }
    #pragma unroll
    for (int o = 16; o; o >>= 1) ss += __shfl_xor_sync(0xffffffffu, ss, o);
    if (lane == 0) red[wid] = ss;
    __syncthreads();
    if (tid == 0) {
        float t = 0.f;
        #pragma unroll
        for (int i = 0; i < 8; i++) t += red[i];
        s_rstd = rsqrtf(t / (float)DIM + EPS);
    }
    __syncthreads();
    const float rstd = s_rstd;

    const float* crow = cosf + (size_t)s * HDIM;
    const float* srow = sinf + (size_t)s * HDIM;
    for (int p = tid; p < DIM / 2; p += 256) {
        int head = p >> 6;
        int t    = p & 63;
        int e0 = head * HDIM + 2 * t;
        float xe = row[e0]     * rstd * w[e0];
        float xo = row[e0 + 1] * rstd * w[e0 + 1];
        float c  = crow[2 * t];
        float sn = srow[2 * t + 1];
        float oe = xe * c - xo * sn;
        float oo = xe * sn + xo * c;

        __nv_bfloat16 he = __float2bfloat16(oe);
        __nv_bfloat16 ho = __float2bfloat16(oo);
        __nv_bfloat162 hp; hp.x = he; hp.y = ho;
        __nv_bfloat162 lp;
        lp.x = __float2bfloat16(oe - __bfloat162float(he));
        lp.y = __float2bfloat16(oo - __bfloat162float(ho));

        __nv_bfloat16* out = dst + ((size_t)s * NHEAD + head) * 256 + 2 * t;
        *(__nv_bfloat162*)(out)       = hp;
        *(__nv_bfloat162*)(out + 128) = lp;
    }
}

// ===========================================================================
// Tensorized flash attention (Q-in-registers, 2 CTAs/SM). Epilogue now
// writes plain fp32 (tf32-rounded) att rows for the tf32 out-GEMM.
// ===========================================================================
#define FC_NT   (S_LEN / 64)       // 32
#define KROWB   528                // 33 x 16B chunks
#define VROWB   272                // 17 x 16B chunks
#define FC_K(st) ((st) * 33792)
#define FC_V(st) (67584 + (st) * 17408)
#define FC_SMEM 102400

__global__ __launch_bounds__(128, 2) void fa_mma(
    const __nv_bfloat16* __restrict__ qH, const __nv_bfloat16* __restrict__ kH,
    const __half* __restrict__ vH, float* __restrict__ att)
{
    extern __shared__ char smraw[];
    const uint32_t sb = smem_u32(smraw);
    const int tid = threadIdx.x, lane = tid & 31, w = tid >> 5;
    const int sub = lane >> 3, l7 = lane & 7;
    const int q0 = blockIdx.x * 64, h = blockIdx.y;
    const int mw = w * 16;

    // ---- stage Q tile through K0 buffer, then ldmatrix into registers ----
    #pragma unroll
    for (int i = 0; i < 16; i++) {
        int f = tid + i * 128, r = f >> 5, c = f & 31;
        cp16(sb + FC_K(0) + r * KROWB + c * 16,
             qH + ((size_t)(q0 + r) * NHEAD + h) * 256 + c * 8);
    }
    CP_COMMIT();
    CP_WAIT0();
    __syncthreads();

    uint32_t qhi[8][4], qlo[8][4];
    {
        const uint32_t qb = sb + FC_K(0)
                          + (mw + ((sub & 1) << 3) + l7) * KROWB;
        #pragma unroll
        for (int ks = 0; ks < 8; ks++) {
            ldm_x4(qhi[ks], qb + (2 * ks + (sub >> 1)) * 16);
            ldm_x4(qlo[ks], qb + (16 + 2 * ks + (sub >> 1)) * 16);
        }
    }
    __syncthreads();

    auto load_kv = [&](int st, int kt) {
        const int kb = kt * 64;
        #pragma unroll
        for (int i = 0; i < 16; i++) {
            int f = tid + i * 128, r = f >> 5, c = f & 31;
            cp16(sb + FC_K(st) + r * KROWB + c * 16,
                 kH + ((size_t)(kb + r) * NHEAD + h) * 256 + c * 8);
        }
        #pragma unroll
        for (int i = 0; i < 8; i++) {
            int f = tid + i * 128, r = f >> 4, c = f & 15;
            cp16(sb + FC_V(st) + r * VROWB + c * 16,
                 vH + (size_t)(kb + r) * DIM + h * HDIM + c * 8);
        }
    };
    load_kv(0, 0); CP_COMMIT();
    load_kv(1, 1); CP_COMMIT();

    float m0 = -1e30f, m1 = -1e30f, l0 = 0.f, l1 = 0.f;
    float oacc[16][4];
    #pragma unroll
    for (int i = 0; i < 16; i++)
        #pragma unroll
        for (int j = 0; j < 4; j++) oacc[i][j] = 0.f;

    #pragma unroll 1
    for (int kt = 0; kt < FC_NT; kt++) {
        CP_WAIT1();
        __syncthreads();
        const uint32_t Ks = sb + FC_K(kt & 1);
        const uint32_t Vs = sb + FC_V(kt & 1);
        const uint32_t kbase = Ks + (((sub >> 1) << 3) + l7) * KROWB;

        float s[8][4];
        #pragma unroll
        for (int j = 0; j < 8; j++)
            #pragma unroll
            for (int q = 0; q < 4; q++) s[j][q] = 0.f;

        #pragma unroll
        for (int seg = 0; seg < 3; seg++) {
            const int boff = (seg == 1) ? 16 : 0;
            #pragma unroll
            for (int ks = 0; ks < 8; ks++) {
                const uint32_t* af = (seg == 2) ? qlo[ks] : qhi[ks];
                const uint32_t ca = (boff + 2 * ks + (sub & 1)) * 16;
                #pragma unroll
                for (int p = 0; p < 4; p++) {
                    uint32_t bf[4];
                    ldm_x4(bf, kbase + p * 16 * KROWB + ca);
                    mma_bf16(s[2 * p],     af, bf);
                    mma_bf16(s[2 * p + 1], af, bf + 2);
                }
            }
        }

        float rmx0 = -1e30f, rmx1 = -1e30f;
        #pragma unroll
        for (int j = 0; j < 8; j++) {
            s[j][0] *= ATT_SCALE; s[j][1] *= ATT_SCALE;
            s[j][2] *= ATT_SCALE; s[j][3] *= ATT_SCALE;
            rmx0 = fmaxf(rmx0, fmaxf(s[j][0], s[j][1]));
            rmx1 = fmaxf(rmx1, fmaxf(s[j][2], s[j][3]));
        }
        rmx0 = fmaxf(rmx0, __shfl_xor_sync(0xffffffffu, rmx0, 1));
        rmx0 = fmaxf(rmx0, __shfl_xor_sync(0xffffffffu, rmx0, 2));
        rmx1 = fmaxf(rmx1, __shfl_xor_sync(0xffffffffu, rmx1, 1));
        rmx1 = fmaxf(rmx1, __shfl_xor_sync(0xffffffffu, rmx1, 2));

        float nm0 = fmaxf(m0, rmx0), nm1 = fmaxf(m1, rmx1);
        float a0 = __expf(m0 - nm0), a1 = __expf(m1 - nm1);
        m0 = nm0; m1 = nm1;

        float ls0 = 0.f, ls1 = 0.f;
        #pragma unroll
        for (int j = 0; j < 8; j++) {
            s[j][0] = __expf(s[j][0] - nm0);
            s[j][1] = __expf(s[j][1] - nm0);
            s[j][2] = __expf(s[j][2] - nm1);
            s[j][3] = __expf(s[j][3] - nm1);
            ls0 += s[j][0] + s[j][1];
            ls1 += s[j][2] + s[j][3];
        }
        ls0 += __shfl_xor_sync(0xffffffffu, ls0, 1);
        ls0 += __shfl_xor_sync(0xffffffffu, ls0, 2);
        ls1 += __shfl_xor_sync(0xffffffffu, ls1, 1);
        ls1 += __shfl_xor_sync(0xffffffffu, ls1, 2);
        l0 = l0 * a0 + ls0;
        l1 = l1 * a1 + ls1;

        #pragma unroll
        for (int nb = 0; nb < 16; nb++) {
            oacc[nb][0] *= a0; oacc[nb][1] *= a0;
            oacc[nb][2] *= a1; oacc[nb][3] *= a1;
        }

        #pragma unroll
        for (int kb = 0; kb < 4; kb++) {
            uint32_t a[4];
            a[0] = f22h2(s[2 * kb][0],     s[2 * kb][1]);
            a[1] = f22h2(s[2 * kb][2],     s[2 * kb][3]);
            a[2] = f22h2(s[2 * kb + 1][0], s[2 * kb + 1][1]);
            a[3] = f22h2(s[2 * kb + 1][2], s[2 * kb + 1][3]);
            const uint32_t vb = Vs + (kb * 16 + ((sub & 1) << 3) + l7) * VROWB
                              + (((sub >> 1) << 3)) * 2;
            #pragma unroll
            for (int nb = 0; nb < 16; nb += 2) {
                uint32_t bf[4];
                ldm_x4t(bf, vb + nb * 16);
                mma_f16(oacc[nb],     a, bf);
                mma_f16(oacc[nb + 1], a, bf + 2);
            }
        }

        __syncthreads();
        if (kt + 2 < FC_NT) load_kv(kt & 1, kt + 2);
        CP_COMMIT();
    }

    // ---- epilogue: O/l -> att fp32 (tf32-rounded for the out-GEMM) ----
    const int g = lane >> 2, tq = lane & 3;
    const float inv0 = 1.f / l0, inv1 = 1.f / l1;
    float* r0p = att + (size_t)(q0 + mw + g) * DIM + h * HDIM;
    float* r1p = att + (size_t)(q0 + mw + g + 8) * DIM + h * HDIM;
    #pragma unroll
    for (int nb = 0; nb < 16; nb++) {
        int c = nb * 8 + tq * 2;
        float2 o0, o1;
        o0.x = rna(oacc[nb][0] * inv0); o0.y = rna(oacc[nb][1] * inv0);
        o1.x = rna(oacc[nb][2] * inv1); o1.y = rna(oacc[nb][3] * inv1);
        *(float2*)(r0p + c) = o0;
        *(float2*)(r1p + c) = o1;
    }
}

// ===========================================================================
// kernel_launch
// ===========================================================================
extern "C" void kernel_launch(void* const* d_in, const int* in_sizes, int n_in,
                              void* d_out, int out_size)
{
    const float* hs     = (const float*)d_in[0];
    const float* cosf_  = (const float*)d_in[1];
    const float* sinf_  = (const float*)d_in[2];
    const float* w_qkv  = (const float*)d_in[3];
    const float* b_qkv  = (const float*)d_in[4];
    const float* w_qn   = (const float*)d_in[5];
    const float* w_kn   = (const float*)d_in[6];
    const float* w_out  = (const float*)d_in[7];
    const float* b_out  = (const float*)d_in[8];
    float* out = (float*)d_out;

    float *qkv, *att, *hsR, *wqkvT, *woutT;
    __nv_bfloat16 *qH, *kH;
    __half* vH;
    cudaGetSymbolAddress((void**)&qkv,   g_qkv);
    cudaGetSymbolAddress((void**)&att,   g_att);
    cudaGetSymbolAddress((void**)&hsR,   g_hsR);
    cudaGetSymbolAddress((void**)&wqkvT, g_wqkvT);
    cudaGetSymbolAddress((void**)&woutT, g_woutT);
    cudaGetSymbolAddress((void**)&qH,    g_qH);
    cudaGetSymbolAddress((void**)&kH,    g_kH);
    cudaGetSymbolAddress((void**)&vH,    g_vH);

    cudaFuncSetAttribute(gemm_t32,
                         cudaFuncAttributeMaxDynamicSharedMemorySize, T_SMEM);
    cudaFuncSetAttribute(fa_mma,
                         cudaFuncAttributeMaxDynamicSharedMemorySize, FC_SMEM);

    // --- pre-passes: weight transposes (tf32-rounded) + hs round ---
    transpose_t32<<<dim3(QKVW/32, DIM/32), dim3(32,8)>>>(w_qkv, wqkvT, QKVW);
    transpose_t32<<<dim3(DIM/32,  DIM/32), dim3(32,8)>>>(w_out, woutT, DIM);
    round_t32<<<2048, 256>>>(hs, hsR, (S_LEN*DIM)/4);

    // --- qkv = hs @ w_qkv + b  (tf32; v columns emitted fp16 to vH) ---
    gemm_t32<<<dim3(S_LEN/128, QKVW/128), 128, T_SMEM>>>(
        hsR, wqkvT, b_qkv, qkv, vH, QKVW, DIM);

    // --- rmsnorm + rope -> bf16 [hi|lo] q/k ---
    normrope_kernel<<<dim3(S_LEN, 2), 256>>>(qkv, w_qn, w_kn, cosf_, sinf_,
                                             qH, kH);

    // --- tensorized flash attention -> att fp32 (tf32-valued) ---
    fa_mma<<<dim3(S_LEN/64, NHEAD), 128, FC_SMEM>>>(qH, kH, vH, att);

    // --- out = att @ w_out + b  (tf32) ---
    gemm_t32<<<dim3(S_LEN/128, DIM/128), 128, T_SMEM>>>(
        att, woutT, b_out, out, nullptr, DIM, DIM);
}

// round 10
// speedup vs baseline: 5.6284x; 1.1003x over previous
#include <cuda_runtime.h>
#include <cuda_bf16.h>
#include <cuda_fp16.h>
#include <cstdint>
#include <math.h>

// ---------------------------------------------------------------------------
// StaticSelfAttention: B=1, S=2048, DIM=5120, H=40, D=128, fp32.
// Round 10: tf32 GEMMs (unchanged) + FA with single-pass fp16 QK^T
//           (q/k fp16 per-head, 68KB smem, up to 3 CTAs/SM).
// ---------------------------------------------------------------------------

#define S_LEN 2048
#define DIM   5120
#define NHEAD 40
#define HDIM  128
#define QKVW  (3*DIM)          // 15360
#define EPS   1e-6f
#define ATT_SCALE 0.08838834764831845f   // 128^-0.5

// -------------------- scratch (__device__ globals; no allocs) --------------
__device__ float g_qkv[(size_t)S_LEN * QKVW];             // q,k fp32 (v -> vH)
__device__ float g_att[(size_t)S_LEN * DIM];              // FA out, tf32-valued
__device__ float g_hsR[(size_t)S_LEN * DIM];              // hs, tf32-rounded
__device__ float g_wqkvT[(size_t)QKVW * DIM];             // [N][K] tf32-valued
__device__ float g_woutT[(size_t)DIM  * DIM];             // [N][K] tf32-valued
__device__ __half g_qF[(size_t)S_LEN * NHEAD * HDIM];     // [s][h][d] fp16
__device__ __half g_kF[(size_t)S_LEN * NHEAD * HDIM];     // [s][h][d] fp16
__device__ __half g_vH[(size_t)S_LEN * DIM];              // [s][h*128+d] fp16

// -------------------- PTX helpers (baseline ISA only) ----------------------
__device__ __forceinline__ uint32_t smem_u32(const void* p) {
    uint32_t a;
    asm("{ .reg .u64 t; cvta.to.shared.u64 t, %1; cvt.u32.u64 %0, t; }"
        : "=r"(a) : "l"(p));
    return a;
}
__device__ __forceinline__ void cp16(uint32_t dst, const void* src) {
    asm volatile("cp.async.cg.shared.global [%0], [%1], 16;\n"
                 :: "r"(dst), "l"(src));
}
#define CP_COMMIT() asm volatile("cp.async.commit_group;\n" ::: "memory")
#define CP_WAIT1()  asm volatile("cp.async.wait_group 1;\n" ::: "memory")
#define CP_WAIT0()  asm volatile("cp.async.wait_group 0;\n" ::: "memory")

__device__ __forceinline__ void ldm_x4(uint32_t* r, uint32_t a) {
    asm volatile("ldmatrix.sync.aligned.m8n8.x4.shared.b16 {%0,%1,%2,%3}, [%4];\n"
                 : "=r"(r[0]), "=r"(r[1]), "=r"(r[2]), "=r"(r[3]) : "r"(a));
}
__device__ __forceinline__ void ldm_x4t(uint32_t* r, uint32_t a) {
    asm volatile("ldmatrix.sync.aligned.m8n8.x4.trans.shared.b16 {%0,%1,%2,%3}, [%4];\n"
                 : "=r"(r[0]), "=r"(r[1]), "=r"(r[2]), "=r"(r[3]) : "r"(a));
}
__device__ __forceinline__ void mma_f16(float* d, const uint32_t* a,
                                        const uint32_t* b) {
    asm volatile(
        "mma.sync.aligned.m16n8k16.row.col.f32.f16.f16.f32 "
        "{%0,%1,%2,%3}, {%4,%5,%6,%7}, {%8,%9}, {%0,%1,%2,%3};\n"
        : "+f"(d[0]), "+f"(d[1]), "+f"(d[2]), "+f"(d[3])
        : "r"(a[0]), "r"(a[1]), "r"(a[2]), "r"(a[3]), "r"(b[0]), "r"(b[1]));
}
__device__ __forceinline__ void mma_t32(float* d, const uint32_t* a,
                                        const uint32_t* b) {
    asm volatile(
        "mma.sync.aligned.m16n8k8.row.col.f32.tf32.tf32.f32 "
        "{%0,%1,%2,%3}, {%4,%5,%6,%7}, {%8,%9}, {%0,%1,%2,%3};\n"
        : "+f"(d[0]), "+f"(d[1]), "+f"(d[2]), "+f"(d[3])
        : "r"(a[0]), "r"(a[1]), "r"(a[2]), "r"(a[3]), "r"(b[0]), "r"(b[1]));
}
__device__ __forceinline__ uint32_t f22h2(float x, float y) {
    __half2 t = __floats2half2_rn(x, y);
    return *reinterpret_cast<uint32_t*>(&t);
}
__device__ __forceinline__ float rna(float x) {
    uint32_t u;
    asm("cvt.rna.tf32.f32 %0, %1;" : "=r"(u) : "f"(x));
    return __uint_as_float(u);
}

// ===========================================================================
// Pre-pass 1: elementwise tf32 RNA round, fp32 -> fp32(tf32-valued)
// ===========================================================================
__global__ __launch_bounds__(256) void round_t32(
    const float* __restrict__ X, float* __restrict__ Y, int n4)
{
    for (int i = blockIdx.x * 256 + threadIdx.x; i < n4;
         i += gridDim.x * 256) {
        float4 v = ((const float4*)X)[i];
        float4 o;
        o.x = rna(v.x); o.y = rna(v.y); o.z = rna(v.z); o.w = rna(v.w);
        ((float4*)Y)[i] = o;
    }
}

// ===========================================================================
// Pre-pass 2: W[K=DIM][N] fp32 -> T[N][K=DIM] fp32 (tf32 RNA-rounded)
// ===========================================================================
__global__ void transpose_t32(const float* __restrict__ W,
                              float* __restrict__ T, int N)
{
    __shared__ float t[32][33];
    const int n0 = blockIdx.x * 32, k0 = blockIdx.y * 32;
    const int x = threadIdx.x, y = threadIdx.y;   // 32 x 8
    #pragma unroll
    for (int i = 0; i < 32; i += 8)
        t[y + i][x] = W[(size_t)(k0 + y + i) * N + n0 + x];
    __syncthreads();
    #pragma unroll
    for (int i = 0; i < 32; i += 8)
        T[(size_t)(n0 + y + i) * DIM + k0 + x] = rna(t[x][y + i]);
}

// ===========================================================================
// TF32 GEMM (unchanged from round 9; tensor=77%).
// ===========================================================================
#define T_BK      32
#define T_STAGES  3
#define T_STAGE_B 32768
#define T_SMEM    (T_STAGES * T_STAGE_B)

__device__ __forceinline__ uint32_t tsw(int r, int c) {
    return (uint32_t)(r * 128 + ((c ^ (r & 7)) << 4));
}

__global__ __launch_bounds__(128, 2) void gemm_t32(
    const float* __restrict__ A, const float* __restrict__ Bm,
    const float* __restrict__ bias, float* __restrict__ C,
    __half* __restrict__ vout, int N, int K)
{
    extern __shared__ char smraw[];
    const uint32_t sbase = smem_u32(smraw);

    const int tid = threadIdx.x, lane = tid & 31, wid = tid >> 5;
    const int row0 = blockIdx.x * 128;
    const int col0 = blockIdx.y * 128;
    const int mw = (wid >> 1) * 64;
    const int nw = (wid & 1) * 64;
    const int sub = lane >> 3, l7 = lane & 7;

    float acc[4][8][4];
    #pragma unroll
    for (int i = 0; i < 4; i++)
        #pragma unroll
        for (int j = 0; j < 8; j++)
            #pragma unroll
            for (int q = 0; q < 4; q++) acc[i][j][q] = 0.f;

    const int NIT = K / T_BK;

    auto load_stage = [&](int st, int k0) {
        const uint32_t sA = sbase + st * T_STAGE_B;
        const uint32_t sB = sA + 16384;
        #pragma unroll
        for (int i = 0; i < 8; i++) {
            int f = tid + i * 128;
            int r = f >> 3, c = f & 7;
            uint32_t so = tsw(r, c);
            cp16(sA + so, A  + (size_t)(row0 + r) * K + k0 + c * 4);
            cp16(sB + so, Bm + (size_t)(col0 + r) * K + k0 + c * 4);
        }
    };

    load_stage(0, 0);       CP_COMMIT();
    load_stage(1, T_BK);    CP_COMMIT();

    #pragma unroll 1
    for (int it = 0; it < NIT; it++) {
        CP_WAIT1();
        __syncthreads();
        const uint32_t uA = sbase + (it % 3) * T_STAGE_B;
        const uint32_t uB = uA + 16384;

        #pragma unroll
        for (int kk = 0; kk < 4; kk++) {
            uint32_t a[4][4];
            #pragma unroll
            for (int i = 0; i < 4; i++) {
                int r = mw + i * 16 + ((sub & 1) << 3) + l7;
                int c = kk * 2 + (sub >> 1);
                ldm_x4(a[i], uA + tsw(r, c));
            }
            #pragma unroll
            for (int j = 0; j < 4; j++) {
                uint32_t b[4];
                int r = nw + j * 16 + ((sub >> 1) << 3) + l7;
                int c = kk * 2 + (sub & 1);
                ldm_x4(b, uB + tsw(r, c));
                #pragma unroll
                for (int i = 0; i < 4; i++) {
                    mma_t32(acc[i][2 * j],     a[i], b);
                    mma_t32(acc[i][2 * j + 1], a[i], b + 2);
                }
            }
        }

        const int nld = it + 2;
        if (nld < NIT) load_stage(nld % 3, nld * T_BK);
        CP_COMMIT();
    }

    const int g = lane >> 2, tq = lane & 3;
    const bool vtile = (vout != nullptr) && (col0 >= 2 * DIM);
    #pragma unroll
    for (int i = 0; i < 4; i++) {
        int r = row0 + mw + i * 16 + g;
        #pragma unroll
        for (int j = 0; j < 8; j++) {
            int c = col0 + nw + j * 8 + tq * 2;
            float bx = bias[c], by = bias[c + 1];
            float x0 = acc[i][j][0] + bx, y0 = acc[i][j][1] + by;
            float x1 = acc[i][j][2] + bx, y1 = acc[i][j][3] + by;
            if (vtile) {
                int vc = c - 2 * DIM;
                __half2 h0 = __floats2half2_rn(x0, y0);
                __half2 h1 = __floats2half2_rn(x1, y1);
                *(__half2*)(vout + (size_t)r * DIM + vc)       = h0;
                *(__half2*)(vout + (size_t)(r + 8) * DIM + vc) = h1;
            } else {
                float2 o0; o0.x = x0; o0.y = y0;
                float2 o1; o1.x = x1; o1.y = y1;
                *(float2*)(C + (size_t)r * N + c)       = o0;
                *(float2*)(C + (size_t)(r + 8) * N + c) = o1;
            }
        }
    }
}

// ===========================================================================
// Fused RMSNorm + RoPE -> fp16 q/k per head [s][h][128].
// grid (S, 2): y=0 q, y=1 k. 256 threads.
// ===========================================================================
__global__ __launch_bounds__(256) void normrope_kernel(
    const float* __restrict__ qkv,
    const float* __restrict__ w_qn, const float* __restrict__ w_kn,
    const float* __restrict__ cosf, const float* __restrict__ sinf,
    __half* __restrict__ qF, __half* __restrict__ kF)
{
    const int s   = blockIdx.x;
    const int sel = blockIdx.y;
    const int tid = threadIdx.x;

    const float* row = qkv + (size_t)s * QKVW + sel * DIM;
    const float* w = sel ? w_kn : w_qn;
    __half* dst = sel ? kF : qF;

    const int lane = tid & 31, wid = tid >> 5;
    __shared__ float red[8];
    __shared__ float s_rstd;

    float ss = 0.f;
    const float4* row4 = (const float4*)row;
    for (int i = tid; i < DIM / 4; i += 256) {
        float4 v = row4[i];
        ss += v.x * v.x + v.y * v.y + v.z * v.z + v.w * v.w;
    }
    #pragma unroll
    for (int o = 16; o; o >>= 1) ss += __shfl_xor_sync(0xffffffffu, ss, o);
    if (lane == 0) red[wid] = ss;
    __syncthreads();
    if (tid == 0) {
        float t = 0.f;
        #pragma unroll
        for (int i = 0; i < 8; i++) t += red[i];
        s_rstd = rsqrtf(t / (float)DIM + EPS);
    }
    __syncthreads();
    const float rstd = s_rstd;

    const float* crow = cosf + (size_t)s * HDIM;
    const float* srow = sinf + (size_t)s * HDIM;
    for (int p = tid; p < DIM / 2; p += 256) {
        int head = p >> 6;
        int t    = p & 63;
        int e0 = head * HDIM + 2 * t;
        float xe = row[e0]     * rstd * w[e0];
        float xo = row[e0 + 1] * rstd * w[e0 + 1];
        float c  = crow[2 * t];
        float sn = srow[2 * t + 1];
        float oe = xe * c - xo * sn;
        float oo = xe * sn + xo * c;

        __half* out = dst + ((size_t)s * NHEAD + head) * HDIM + 2 * t;
        *(__half2*)out = __floats2half2_rn(oe, oo);
    }
}

// ===========================================================================
// Tensorized flash attention v4: fp16 single-pass QK^T + fp16 PV.
//   Br=64 (4 warps), Bc=64. Q in registers (8 fp16 frags). K/V double-buffered
//   cp.async, 272B rows (17 chunks, odd -> conflict-free). smem 68KB.
// ===========================================================================
#define FD_NT   (S_LEN / 64)       // 32
#define ROWB    272                // 17 x 16B chunks (16 data + 1 pad)
#define FD_K(st) ((st) * 17408)
#define FD_V(st) (34816 + (st) * 17408)
#define FD_SMEM 69632

__global__ __launch_bounds__(128, 2) void fa_mma(
    const __half* __restrict__ qF, const __half* __restrict__ kF,
    const __half* __restrict__ vH, float* __restrict__ att)
{
    extern __shared__ char smraw[];
    const uint32_t sb = smem_u32(smraw);
    const int tid = threadIdx.x, lane = tid & 31, w = tid >> 5;
    const int sub = lane >> 3, l7 = lane & 7;
    const int q0 = blockIdx.x * 64, h = blockIdx.y;
    const int mw = w * 16;

    // ---- stage Q tile through K0 buffer, then ldmatrix into registers ----
    #pragma unroll
    for (int i = 0; i < 8; i++) {
        int f = tid + i * 128, r = f >> 4, c = f & 15;
        cp16(sb + FD_K(0) + r * ROWB + c * 16,
             qF + ((size_t)(q0 + r) * NHEAD + h) * HDIM + c * 8);
    }
    CP_COMMIT();
    CP_WAIT0();
    __syncthreads();

    uint32_t qf[8][4];
    {
        const uint32_t qb = sb + FD_K(0)
                          + (mw + ((sub & 1) << 3) + l7) * ROWB;
        #pragma unroll
        for (int ks = 0; ks < 8; ks++)
            ldm_x4(qf[ks], qb + (2 * ks + (sub >> 1)) * 16);
    }
    __syncthreads();

    auto load_kv = [&](int st, int kt) {
        const int kb = kt * 64;
        #pragma unroll
        for (int i = 0; i < 8; i++) {
            int f = tid + i * 128, r = f >> 4, c = f & 15;
            cp16(sb + FD_K(st) + r * ROWB + c * 16,
                 kF + ((size_t)(kb + r) * NHEAD + h) * HDIM + c * 8);
        }
        #pragma unroll
        for (int i = 0; i < 8; i++) {
            int f = tid + i * 128, r = f >> 4, c = f & 15;
            cp16(sb + FD_V(st) + r * ROWB + c * 16,
                 vH + (size_t)(kb + r) * DIM + h * HDIM + c * 8);
        }
    };
    load_kv(0, 0); CP_COMMIT();
    load_kv(1, 1); CP_COMMIT();

    float m0 = -1e30f, m1 = -1e30f, l0 = 0.f, l1 = 0.f;
    float oacc[16][4];
    #pragma unroll
    for (int i = 0; i < 16; i++)
        #pragma unroll
        for (int j = 0; j < 4; j++) oacc[i][j] = 0.f;

    #pragma unroll 1
    for (int kt = 0; kt < FD_NT; kt++) {
        CP_WAIT1();
        __syncthreads();
        const uint32_t Ks = sb + FD_K(kt & 1);
        const uint32_t Vs = sb + FD_V(kt & 1);
        const uint32_t kbase = Ks + ((((sub >> 1) << 3)) + l7) * ROWB;

        // ---- S = Q K^T (fp16 single pass, k=128) ----
        float s[8][4];
        #pragma unroll
        for (int j = 0; j < 8; j++)
            #pragma unroll
            for (int q = 0; q < 4; q++) s[j][q] = 0.f;

        #pragma unroll
        for (int ks = 0; ks < 8; ks++) {
            const uint32_t ca = (2 * ks + (sub & 1)) * 16;
            #pragma unroll
            for (int p = 0; p < 4; p++) {
                uint32_t bf[4];
                ldm_x4(bf, kbase + p * 16 * ROWB + ca);
                mma_f16(s[2 * p],     qf[ks], bf);
                mma_f16(s[2 * p + 1], qf[ks], bf + 2);
            }
        }

        // ---- register softmax ----
        float rmx0 = -1e30f, rmx1 = -1e30f;
        #pragma unroll
        for (int j = 0; j < 8; j++) {
            s[j][0] *= ATT_SCALE; s[j][1] *= ATT_SCALE;
            s[j][2] *= ATT_SCALE; s[j][3] *= ATT_SCALE;
            rmx0 = fmaxf(rmx0, fmaxf(s[j][0], s[j][1]));
            rmx1 = fmaxf(rmx1, fmaxf(s[j][2], s[j][3]));
        }
        rmx0 = fmaxf(rmx0, __shfl_xor_sync(0xffffffffu, rmx0, 1));
        rmx0 = fmaxf(rmx0, __shfl_xor_sync(0xffffffffu, rmx0, 2));
        rmx1 = fmaxf(rmx1, __shfl_xor_sync(0xffffffffu, rmx1, 1));
        rmx1 = fmaxf(rmx1, __shfl_xor_sync(0xffffffffu, rmx1, 2));

        float nm0 = fmaxf(m0, rmx0), nm1 = fmaxf(m1, rmx1);
        float a0 = __expf(m0 - nm0), a1 = __expf(m1 - nm1);
        m0 = nm0; m1 = nm1;

        float ls0 = 0.f, ls1 = 0.f;
        #pragma unroll
        for (int j = 0; j < 8; j++) {
            s[j][0] = __expf(s[j][0] - nm0);
            s[j][1] = __expf(s[j][1] - nm0);
            s[j][2] = __expf(s[j][2] - nm1);
            s[j][3] = __expf(s[j][3] - nm1);
            ls0 += s[j][0] + s[j][1];
            ls1 += s[j][2] + s[j][3];
        }
        ls0 += __shfl_xor_sync(0xffffffffu, ls0, 1);
        ls0 += __shfl_xor_sync(0xffffffffu, ls0, 2);
        ls1 += __shfl_xor_sync(0xffffffffu, ls1, 1);
        ls1 += __shfl_xor_sync(0xffffffffu, ls1, 2);
        l0 = l0 * a0 + ls0;
        l1 = l1 * a1 + ls1;

        #pragma unroll
        for (int nb = 0; nb < 16; nb++) {
            oacc[nb][0] *= a0; oacc[nb][1] *= a0;
            oacc[nb][2] *= a1; oacc[nb][3] *= a1;
        }

        // ---- O += P @ V (fp16) ----
        #pragma unroll
        for (int kb = 0; kb < 4; kb++) {
            uint32_t a[4];
            a[0] = f22h2(s[2 * kb][0],     s[2 * kb][1]);
            a[1] = f22h2(s[2 * kb][2],     s[2 * kb][3]);
            a[2] = f22h2(s[2 * kb + 1][0], s[2 * kb + 1][1]);
            a[3] = f22h2(s[2 * kb + 1][2], s[2 * kb + 1][3]);
            const uint32_t vb = Vs + (kb * 16 + ((sub & 1) << 3) + l7) * ROWB
                              + (((sub >> 1) << 3)) * 2;
            #pragma unroll
            for (int nb = 0; nb < 16; nb += 2) {
                uint32_t bf[4];
                ldm_x4t(bf, vb + nb * 16);
                mma_f16(oacc[nb],     a, bf);
                mma_f16(oacc[nb + 1], a, bf + 2);
            }
        }

        __syncthreads();
        if (kt + 2 < FD_NT) load_kv(kt & 1, kt + 2);
        CP_COMMIT();
    }

    // ---- epilogue: O/l -> att fp32 (tf32-rounded for the out-GEMM) ----
    const int g = lane >> 2, tq = lane & 3;
    const float inv0 = 1.f / l0, inv1 = 1.f / l1;
    float* r0p = att + (size_t)(q0 + mw + g) * DIM + h * HDIM;
    float* r1p = att + (size_t)(q0 + mw + g + 8) * DIM + h * HDIM;
    #pragma unroll
    for (int nb = 0; nb < 16; nb++) {
        int c = nb * 8 + tq * 2;
        float2 o0, o1;
        o0.x = rna(oacc[nb][0] * inv0); o0.y = rna(oacc[nb][1] * inv0);
        o1.x = rna(oacc[nb][2] * inv1); o1.y = rna(oacc[nb][3] * inv1);
        *(float2*)(r0p + c) = o0;
        *(float2*)(r1p + c) = o1;
    }
}

// ===========================================================================
// kernel_launch
// ===========================================================================
extern "C" void kernel_launch(void* const* d_in, const int* in_sizes, int n_in,
                              void* d_out, int out_size)
{
    const float* hs     = (const float*)d_in[0];
    const float* cosf_  = (const float*)d_in[1];
    const float* sinf_  = (const float*)d_in[2];
    const float* w_qkv  = (const float*)d_in[3];
    const float* b_qkv  = (const float*)d_in[4];
    const float* w_qn   = (const float*)d_in[5];
    const float* w_kn   = (const float*)d_in[6];
    const float* w_out  = (const float*)d_in[7];
    const float* b_out  = (const float*)d_in[8];
    float* out = (float*)d_out;

    float *qkv, *att, *hsR, *wqkvT, *woutT;
    __half *qF, *kF, *vH;
    cudaGetSymbolAddress((void**)&qkv,   g_qkv);
    cudaGetSymbolAddress((void**)&att,   g_att);
    cudaGetSymbolAddress((void**)&hsR,   g_hsR);
    cudaGetSymbolAddress((void**)&wqkvT, g_wqkvT);
    cudaGetSymbolAddress((void**)&woutT, g_woutT);
    cudaGetSymbolAddress((void**)&qF,    g_qF);
    cudaGetSymbolAddress((void**)&kF,    g_kF);
    cudaGetSymbolAddress((void**)&vH,    g_vH);

    cudaFuncSetAttribute(gemm_t32,
                         cudaFuncAttributeMaxDynamicSharedMemorySize, T_SMEM);
    cudaFuncSetAttribute(fa_mma,
                         cudaFuncAttributeMaxDynamicSharedMemorySize, FD_SMEM);

    // --- pre-passes: weight transposes (tf32-rounded) + hs round ---
    transpose_t32<<<dim3(QKVW/32, DIM/32), dim3(32,8)>>>(w_qkv, wqkvT, QKVW);
    transpose_t32<<<dim3(DIM/32,  DIM/32), dim3(32,8)>>>(w_out, woutT, DIM);
    round_t32<<<2048, 256>>>(hs, hsR, (S_LEN*DIM)/4);

    // --- qkv = hs @ w_qkv + b  (tf32; v columns emitted fp16 to vH) ---
    gemm_t32<<<dim3(S_LEN/128, QKVW/128), 128, T_SMEM>>>(
        hsR, wqkvT, b_qkv, qkv, vH, QKVW, DIM);

    // --- rmsnorm + rope -> fp16 q/k per head ---
    normrope_kernel<<<dim3(S_LEN, 2), 256>>>(qkv, w_qn, w_kn, cosf_, sinf_,
                                             qF, kF);

    // --- flash attention (fp16 QK + fp16 PV) -> att fp32 ---
    fa_mma<<<dim3(S_LEN/64, NHEAD), 128, FD_SMEM>>>(qF, kF, vH, att);

    // --- out = att @ w_out + b  (tf32) ---
    gemm_t32<<<dim3(S_LEN/128, DIM/128), 128, T_SMEM>>>(
        att, woutT, b_out, out, nullptr, DIM, DIM);
}

// round 11
// speedup vs baseline: 9.6812x; 1.7200x over previous
#include <cuda_runtime.h>
#include <cuda_bf16.h>
#include <cuda_fp16.h>
#include <cstdint>
#include <math.h>

// ---------------------------------------------------------------------------
// StaticSelfAttention: B=1, S=2048, DIM=5120, H=40, D=128, fp32.
// Round 11: all-fp16 tensor path. fp16 GEMMs (same mantissa as tf32, 2x
//           MACs/instr), fp16 FA, fp16 intermediates end-to-end.
// ---------------------------------------------------------------------------

#define S_LEN 2048
#define DIM   5120
#define NHEAD 40
#define HDIM  128
#define QKVW  (3*DIM)          // 15360
#define EPS   1e-6f
#define ATT_SCALE 0.08838834764831845f   // 128^-0.5

// -------------------- scratch (__device__ globals; no allocs) --------------
__device__ __half g_hsH[(size_t)S_LEN * DIM];              // hs fp16
__device__ __half g_qk [(size_t)S_LEN * 2 * DIM];          // q,k fp16 [S][2*DIM]
__device__ __half g_attF[(size_t)S_LEN * DIM];             // FA out fp16
__device__ __half g_wqkvT[(size_t)QKVW * DIM];             // [N][K] fp16
__device__ __half g_woutT[(size_t)DIM  * DIM];             // [N][K] fp16
__device__ __half g_qF[(size_t)S_LEN * NHEAD * HDIM];      // [s][h][d] fp16
__device__ __half g_kF[(size_t)S_LEN * NHEAD * HDIM];      // [s][h][d] fp16
__device__ __half g_vH[(size_t)S_LEN * DIM];               // [s][h*128+d] fp16

// -------------------- PTX helpers (baseline ISA only) ----------------------
__device__ __forceinline__ uint32_t smem_u32(const void* p) {
    uint32_t a;
    asm("{ .reg .u64 t; cvta.to.shared.u64 t, %1; cvt.u32.u64 %0, t; }"
        : "=r"(a) : "l"(p));
    return a;
}
__device__ __forceinline__ void cp16(uint32_t dst, const void* src) {
    asm volatile("cp.async.cg.shared.global [%0], [%1], 16;\n"
                 :: "r"(dst), "l"(src));
}
#define CP_COMMIT() asm volatile("cp.async.commit_group;\n" ::: "memory")
#define CP_WAIT2()  asm volatile("cp.async.wait_group 2;\n" ::: "memory")
#define CP_WAIT1()  asm volatile("cp.async.wait_group 1;\n" ::: "memory")
#define CP_WAIT0()  asm volatile("cp.async.wait_group 0;\n" ::: "memory")

__device__ __forceinline__ void ldm_x4(uint32_t* r, uint32_t a) {
    asm volatile("ldmatrix.sync.aligned.m8n8.x4.shared.b16 {%0,%1,%2,%3}, [%4];\n"
                 : "=r"(r[0]), "=r"(r[1]), "=r"(r[2]), "=r"(r[3]) : "r"(a));
}
__device__ __forceinline__ void ldm_x4t(uint32_t* r, uint32_t a) {
    asm volatile("ldmatrix.sync.aligned.m8n8.x4.trans.shared.b16 {%0,%1,%2,%3}, [%4];\n"
                 : "=r"(r[0]), "=r"(r[1]), "=r"(r[2]), "=r"(r[3]) : "r"(a));
}
__device__ __forceinline__ void mma_f16(float* d, const uint32_t* a,
                                        const uint32_t* b) {
    asm volatile(
        "mma.sync.aligned.m16n8k16.row.col.f32.f16.f16.f32 "
        "{%0,%1,%2,%3}, {%4,%5,%6,%7}, {%8,%9}, {%0,%1,%2,%3};\n"
        : "+f"(d[0]), "+f"(d[1]), "+f"(d[2]), "+f"(d[3])
        : "r"(a[0]), "r"(a[1]), "r"(a[2]), "r"(a[3]), "r"(b[0]), "r"(b[1]));
}
__device__ __forceinline__ uint32_t f22h2(float x, float y) {
    __half2 t = __floats2half2_rn(x, y);
    return *reinterpret_cast<uint32_t*>(&t);
}

// ===========================================================================
// Pre-pass 1: fp32 -> fp16 elementwise
// ===========================================================================
__global__ __launch_bounds__(256) void convert_h(
    const float* __restrict__ X, __half* __restrict__ Y, int n2)
{
    for (int i = blockIdx.x * 256 + threadIdx.x; i < n2;
         i += gridDim.x * 256) {
        float2 v = ((const float2*)X)[i];
        ((__half2*)Y)[i] = __floats2half2_rn(v.x, v.y);
    }
}

// ===========================================================================
// Pre-pass 2: W[K=DIM][N] fp32 -> T[N][K=DIM] fp16
// ===========================================================================
__global__ void transpose_h(const float* __restrict__ W,
                            __half* __restrict__ T, int N)
{
    __shared__ float t[32][33];
    const int n0 = blockIdx.x * 32, k0 = blockIdx.y * 32;
    const int x = threadIdx.x, y = threadIdx.y;   // 32 x 8
    #pragma unroll
    for (int i = 0; i < 32; i += 8)
        t[y + i][x] = W[(size_t)(k0 + y + i) * N + n0 + x];
    __syncthreads();
    #pragma unroll
    for (int i = 0; i < 32; i += 8)
        T[(size_t)(n0 + y + i) * DIM + k0 + x] = __float2half_rn(t[x][y + i]);
}

// ===========================================================================
// fp16 GEMM: C = A[M,K] @ Bm[N,K]^T + bias.
//   CTA 128x128, BK=32, 4 warps (warp tile 64x64), 4-stage cp.async.
//   qkout!=null: cols < 2*DIM -> qkout fp16, cols >= 2*DIM -> vout fp16.
//   else: C fp32.
// ===========================================================================
#define G_BK      32
#define G_STAGES  4
#define G_STAGE_B 16384                     // A 8KB + B 8KB
#define G_SMEM    (G_STAGES * G_STAGE_B)    // 64KB

__device__ __forceinline__ uint32_t sw_off(int r, int c) {
    return (uint32_t)(((r << 2) | (c ^ ((r >> 1) & 3))) << 4);
}

__global__ __launch_bounds__(128, 2) void gemm_h(
    const __half* __restrict__ A, const __half* __restrict__ Bm,
    const float* __restrict__ bias, float* __restrict__ C,
    __half* __restrict__ qkout, __half* __restrict__ vout, int N, int K)
{
    extern __shared__ char smraw[];
    const uint32_t sbase = smem_u32(smraw);

    const int tid = threadIdx.x, lane = tid & 31, wid = tid >> 5;
    const int row0 = blockIdx.x * 128;
    const int col0 = blockIdx.y * 128;
    const int mw = (wid >> 1) * 64;
    const int nw = (wid & 1) * 64;
    const int sub = lane >> 3, l7 = lane & 7;

    float acc[4][8][4];
    #pragma unroll
    for (int i = 0; i < 4; i++)
        #pragma unroll
        for (int j = 0; j < 8; j++)
            #pragma unroll
            for (int q = 0; q < 4; q++) acc[i][j][q] = 0.f;

    const int NIT = K / G_BK;      // 160

    auto load_stage = [&](int st, int k0) {
        const uint32_t sA = sbase + st * G_STAGE_B;
        const uint32_t sB = sA + 8192;
        #pragma unroll
        for (int i = 0; i < 4; i++) {
            int f = tid + i * 128;
            int r = f >> 2, c = f & 3;
            uint32_t so = sw_off(r, c);
            cp16(sA + so, A  + (size_t)(row0 + r) * K + k0 + c * 8);
            cp16(sB + so, Bm + (size_t)(col0 + r) * K + k0 + c * 8);
        }
    };

    #pragma unroll
    for (int s = 0; s < G_STAGES - 1; s++) { load_stage(s, s * G_BK); CP_COMMIT(); }

    #pragma unroll 1
    for (int it = 0; it < NIT; it++) {
        CP_WAIT2();
        __syncthreads();
        const uint32_t uA = sbase + (it & 3) * G_STAGE_B;
        const uint32_t uB = uA + 8192;

        #pragma unroll
        for (int kk = 0; kk < 2; kk++) {
            const int c0 = kk * 2;
            uint32_t a[4][4], b[4][4];
            #pragma unroll
            for (int i = 0; i < 4; i++) {
                int r = mw + i * 16 + ((sub & 1) << 3) + l7;
                int c = c0 + (sub >> 1);
                ldm_x4(a[i], uA + sw_off(r, c));
            }
            #pragma unroll
            for (int p = 0; p < 4; p++) {
                int r = nw + p * 16 + ((sub >> 1) << 3) + l7;
                int c = c0 + (sub & 1);
                ldm_x4(b[p], uB + sw_off(r, c));
            }
            #pragma unroll
            for (int i = 0; i < 4; i++)
                #pragma unroll
                for (int j = 0; j < 8; j++)
                    mma_f16(acc[i][j], a[i], &b[j >> 1][(j & 1) * 2]);
        }

        const int nld = it + G_STAGES - 1;
        if (nld < NIT) load_stage(nld & 3, nld * G_BK);
        CP_COMMIT();
    }

    const int g = lane >> 2, tq = lane & 3;
    #pragma unroll
    for (int i = 0; i < 4; i++) {
        int r = row0 + mw + i * 16 + g;
        #pragma unroll
        for (int j = 0; j < 8; j++) {
            int c = col0 + nw + j * 8 + tq * 2;
            float bx = bias[c], by = bias[c + 1];
            float x0 = acc[i][j][0] + bx, y0 = acc[i][j][1] + by;
            float x1 = acc[i][j][2] + bx, y1 = acc[i][j][3] + by;
            if (qkout != nullptr) {
                if (col0 < 2 * DIM) {       // q or k slice (fp16)
                    *(__half2*)(qkout + (size_t)r * (2 * DIM) + c)
                        = __floats2half2_rn(x0, y0);
                    *(__half2*)(qkout + (size_t)(r + 8) * (2 * DIM) + c)
                        = __floats2half2_rn(x1, y1);
                } else {                    // v slice (fp16, per-head layout)
                    int vc = c - 2 * DIM;
                    *(__half2*)(vout + (size_t)r * DIM + vc)
                        = __floats2half2_rn(x0, y0);
                    *(__half2*)(vout + (size_t)(r + 8) * DIM + vc)
                        = __floats2half2_rn(x1, y1);
                }
            } else {
                float2 o0; o0.x = x0; o0.y = y0;
                float2 o1; o1.x = x1; o1.y = y1;
                *(float2*)(C + (size_t)r * N + c)       = o0;
                *(float2*)(C + (size_t)(r + 8) * N + c) = o1;
            }
        }
    }
}

// ===========================================================================
// Fused RMSNorm + RoPE: reads fp16 q/k rows, writes fp16 per-head q/k.
// grid (S, 2): y=0 q, y=1 k. 256 threads.
// ===========================================================================
__global__ __launch_bounds__(256) void normrope_kernel(
    const __half* __restrict__ qk,
    const float* __restrict__ w_qn, const float* __restrict__ w_kn,
    const float* __restrict__ cosf, const float* __restrict__ sinf,
    __half* __restrict__ qF, __half* __restrict__ kF)
{
    const int s   = blockIdx.x;
    const int sel = blockIdx.y;
    const int tid = threadIdx.x;

    const __half* row = qk + (size_t)s * (2 * DIM) + sel * DIM;
    const float* w = sel ? w_kn : w_qn;
    __half* dst = sel ? kF : qF;

    const int lane = tid & 31, wid = tid >> 5;
    __shared__ float red[8];
    __shared__ float s_rstd;

    float ss = 0.f;
    const __half2* row2 = (const __half2*)row;
    for (int i = tid; i < DIM / 2; i += 256) {
        float2 v = __half22float2(row2[i]);
        ss += v.x * v.x + v.y * v.y;
    }
    #pragma unroll
    for (int o = 16; o; o >>= 1) ss += __shfl_xor_sync(0xffffffffu, ss, o);
    if (lane == 0) red[wid] = ss;
    __syncthreads();
    if (tid == 0) {
        float t = 0.f;
        #pragma unroll
        for (int i = 0; i < 8; i++) t += red[i];
        s_rstd = rsqrtf(t / (float)DIM + EPS);
    }
    __syncthreads();
    const float rstd = s_rstd;

    const float* crow = cosf + (size_t)s * HDIM;
    const float* srow = sinf + (size_t)s * HDIM;
    for (int p = tid; p < DIM / 2; p += 256) {
        int head = p >> 6;
        int t    = p & 63;
        int e0 = head * HDIM + 2 * t;
        float2 x = __half22float2(row2[p]);   // row2[p] == (row[e0], row[e0+1])
        float xe = x.x * rstd * w[e0];
        float xo = x.y * rstd * w[e0 + 1];
        float c  = crow[2 * t];
        float sn = srow[2 * t + 1];
        float oe = xe * c - xo * sn;
        float oo = xe * sn + xo * c;

        __half* out = dst + ((size_t)s * NHEAD + head) * HDIM + 2 * t;
        *(__half2*)out = __floats2half2_rn(oe, oo);
    }
}

// ===========================================================================
// Tensorized flash attention (fp16 QK + fp16 PV), epilogue -> fp16 att.
// ===========================================================================
#define FD_NT   (S_LEN / 64)       // 32
#define ROWB    272                // 17 x 16B chunks (16 data + 1 pad)
#define FD_K(st) ((st) * 17408)
#define FD_V(st) (34816 + (st) * 17408)
#define FD_SMEM 69632

__global__ __launch_bounds__(128, 2) void fa_mma(
    const __half* __restrict__ qF, const __half* __restrict__ kF,
    const __half* __restrict__ vH, __half* __restrict__ att)
{
    extern __shared__ char smraw[];
    const uint32_t sb = smem_u32(smraw);
    const int tid = threadIdx.x, lane = tid & 31, w = tid >> 5;
    const int sub = lane >> 3, l7 = lane & 7;
    const int q0 = blockIdx.x * 64, h = blockIdx.y;
    const int mw = w * 16;

    // ---- stage Q tile through K0 buffer, then ldmatrix into registers ----
    #pragma unroll
    for (int i = 0; i < 8; i++) {
        int f = tid + i * 128, r = f >> 4, c = f & 15;
        cp16(sb + FD_K(0) + r * ROWB + c * 16,
             qF + ((size_t)(q0 + r) * NHEAD + h) * HDIM + c * 8);
    }
    CP_COMMIT();
    CP_WAIT0();
    __syncthreads();

    uint32_t qf[8][4];
    {
        const uint32_t qb = sb + FD_K(0)
                          + (mw + ((sub & 1) << 3) + l7) * ROWB;
        #pragma unroll
        for (int ks = 0; ks < 8; ks++)
            ldm_x4(qf[ks], qb + (2 * ks + (sub >> 1)) * 16);
    }
    __syncthreads();

    auto load_kv = [&](int st, int kt) {
        const int kb = kt * 64;
        #pragma unroll
        for (int i = 0; i < 8; i++) {
            int f = tid + i * 128, r = f >> 4, c = f & 15;
            cp16(sb + FD_K(st) + r * ROWB + c * 16,
                 kF + ((size_t)(kb + r) * NHEAD + h) * HDIM + c * 8);
        }
        #pragma unroll
        for (int i = 0; i < 8; i++) {
            int f = tid + i * 128, r = f >> 4, c = f & 15;
            cp16(sb + FD_V(st) + r * ROWB + c * 16,
                 vH + (size_t)(kb + r) * DIM + h * HDIM + c * 8);
        }
    };
    load_kv(0, 0); CP_COMMIT();
    load_kv(1, 1); CP_COMMIT();

    float m0 = -1e30f, m1 = -1e30f, l0 = 0.f, l1 = 0.f;
    float oacc[16][4];
    #pragma unroll
    for (int i = 0; i < 16; i++)
        #pragma unroll
        for (int j = 0; j < 4; j++) oacc[i][j] = 0.f;

    #pragma unroll 1
    for (int kt = 0; kt < FD_NT; kt++) {
        CP_WAIT1();
        __syncthreads();
        const uint32_t Ks = sb + FD_K(kt & 1);
        const uint32_t Vs = sb + FD_V(kt & 1);
        const uint32_t kbase = Ks + ((((sub >> 1) << 3)) + l7) * ROWB;

        float s[8][4];
        #pragma unroll
        for (int j = 0; j < 8; j++)
            #pragma unroll
            for (int q = 0; q < 4; q++) s[j][q] = 0.f;

        #pragma unroll
        for (int ks = 0; ks < 8; ks++) {
            const uint32_t ca = (2 * ks + (sub & 1)) * 16;
            #pragma unroll
            for (int p = 0; p < 4; p++) {
                uint32_t bf[4];
                ldm_x4(bf, kbase + p * 16 * ROWB + ca);
                mma_f16(s[2 * p],     qf[ks], bf);
                mma_f16(s[2 * p + 1], qf[ks], bf + 2);
            }
        }

        float rmx0 = -1e30f, rmx1 = -1e30f;
        #pragma unroll
        for (int j = 0; j < 8; j++) {
            s[j][0] *= ATT_SCALE; s[j][1] *= ATT_SCALE;
            s[j][2] *= ATT_SCALE; s[j][3] *= ATT_SCALE;
            rmx0 = fmaxf(rmx0, fmaxf(s[j][0], s[j][1]));
            rmx1 = fmaxf(rmx1, fmaxf(s[j][2], s[j][3]));
        }
        rmx0 = fmaxf(rmx0, __shfl_xor_sync(0xffffffffu, rmx0, 1));
        rmx0 = fmaxf(rmx0, __shfl_xor_sync(0xffffffffu, rmx0, 2));
        rmx1 = fmaxf(rmx1, __shfl_xor_sync(0xffffffffu, rmx1, 1));
        rmx1 = fmaxf(rmx1, __shfl_xor_sync(0xffffffffu, rmx1, 2));

        float nm0 = fmaxf(m0, rmx0), nm1 = fmaxf(m1, rmx1);
        float a0 = __expf(m0 - nm0), a1 = __expf(m1 - nm1);
        m0 = nm0; m1 = nm1;

        float ls0 = 0.f, ls1 = 0.f;
        #pragma unroll
        for (int j = 0; j < 8; j++) {
            s[j][0] = __expf(s[j][0] - nm0);
            s[j][1] = __expf(s[j][1] - nm0);
            s[j][2] = __expf(s[j][2] - nm1);
            s[j][3] = __expf(s[j][3] - nm1);
            ls0 += s[j][0] + s[j][1];
            ls1 += s[j][2] + s[j][3];
        }
        ls0 += __shfl_xor_sync(0xffffffffu, ls0, 1);
        ls0 += __shfl_xor_sync(0xffffffffu, ls0, 2);
        ls1 += __shfl_xor_sync(0xffffffffu, ls1, 1);
        ls1 += __shfl_xor_sync(0xffffffffu, ls1, 2);
        l0 = l0 * a0 + ls0;
        l1 = l1 * a1 + ls1;

        #pragma unroll
        for (int nb = 0; nb < 16; nb++) {
            oacc[nb][0] *= a0; oacc[nb][1] *= a0;
            oacc[nb][2] *= a1; oacc[nb][3] *= a1;
        }

        #pragma unroll
        for (int kb = 0; kb < 4; kb++) {
            uint32_t a[4];
            a[0] = f22h2(s[2 * kb][0],     s[2 * kb][1]);
            a[1] = f22h2(s[2 * kb][2],     s[2 * kb][3]);
            a[2] = f22h2(s[2 * kb + 1][0], s[2 * kb + 1][1]);
            a[3] = f22h2(s[2 * kb + 1][2], s[2 * kb + 1][3]);
            const uint32_t vb = Vs + (kb * 16 + ((sub & 1) << 3) + l7) * ROWB
                              + (((sub >> 1) << 3)) * 2;
            #pragma unroll
            for (int nb = 0; nb < 16; nb += 2) {
                uint32_t bf[4];
                ldm_x4t(bf, vb + nb * 16);
                mma_f16(oacc[nb],     a, bf);
                mma_f16(oacc[nb + 1], a, bf + 2);
            }
        }

        __syncthreads();
        if (kt + 2 < FD_NT) load_kv(kt & 1, kt + 2);
        CP_COMMIT();
    }

    // ---- epilogue: O/l -> att fp16 ----
    const int g = lane >> 2, tq = lane & 3;
    const float inv0 = 1.f / l0, inv1 = 1.f / l1;
    __half* r0p = att + (size_t)(q0 + mw + g) * DIM + h * HDIM;
    __half* r1p = att + (size_t)(q0 + mw + g + 8) * DIM + h * HDIM;
    #pragma unroll
    for (int nb = 0; nb < 16; nb++) {
        int c = nb * 8 + tq * 2;
        *(__half2*)(r0p + c) =
            __floats2half2_rn(oacc[nb][0] * inv0, oacc[nb][1] * inv0);
        *(__half2*)(r1p + c) =
            __floats2half2_rn(oacc[nb][2] * inv1, oacc[nb][3] * inv1);
    }
}

// ===========================================================================
// kernel_launch
// ===========================================================================
extern "C" void kernel_launch(void* const* d_in, const int* in_sizes, int n_in,
                              void* d_out, int out_size)
{
    const float* hs     = (const float*)d_in[0];
    const float* cosf_  = (const float*)d_in[1];
    const float* sinf_  = (const float*)d_in[2];
    const float* w_qkv  = (const float*)d_in[3];
    const float* b_qkv  = (const float*)d_in[4];
    const float* w_qn   = (const float*)d_in[5];
    const float* w_kn   = (const float*)d_in[6];
    const float* w_out  = (const float*)d_in[7];
    const float* b_out  = (const float*)d_in[8];
    float* out = (float*)d_out;

    __half *hsH, *qk, *attF, *wqkvT, *woutT, *qF, *kF, *vH;
    cudaGetSymbolAddress((void**)&hsH,   g_hsH);
    cudaGetSymbolAddress((void**)&qk,    g_qk);
    cudaGetSymbolAddress((void**)&attF,  g_attF);
    cudaGetSymbolAddress((void**)&wqkvT, g_wqkvT);
    cudaGetSymbolAddress((void**)&woutT, g_woutT);
    cudaGetSymbolAddress((void**)&qF,    g_qF);
    cudaGetSymbolAddress((void**)&kF,    g_kF);
    cudaGetSymbolAddress((void**)&vH,    g_vH);

    cudaFuncSetAttribute(gemm_h,
                         cudaFuncAttributeMaxDynamicSharedMemorySize, G_SMEM);
    cudaFuncSetAttribute(fa_mma,
                         cudaFuncAttributeMaxDynamicSharedMemorySize, FD_SMEM);

    // --- pre-passes: weight transposes (fp16) + hs convert ---
    transpose_h<<<dim3(QKVW/32, DIM/32), dim3(32,8)>>>(w_qkv, wqkvT, QKVW);
    transpose_h<<<dim3(DIM/32,  DIM/32), dim3(32,8)>>>(w_out, woutT, DIM);
    convert_h<<<2048, 256>>>(hs, hsH, (S_LEN*DIM)/2);

    // --- qkv = hs @ w_qkv + b  (fp16; q,k -> g_qk, v -> vH) ---
    gemm_h<<<dim3(S_LEN/128, QKVW/128), 128, G_SMEM>>>(
        hsH, wqkvT, b_qkv, nullptr, qk, vH, QKVW, DIM);

    // --- rmsnorm + rope -> fp16 q/k per head ---
    normrope_kernel<<<dim3(S_LEN, 2), 256>>>(qk, w_qn, w_kn, cosf_, sinf_,
                                             qF, kF);

    // --- flash attention (fp16) -> att fp16 ---
    fa_mma<<<dim3(S_LEN/64, NHEAD), 128, FD_SMEM>>>(qF, kF, vH, attF);

    // --- out = att @ w_out + b  (fp16 in, fp32 out) ---
    gemm_h<<<dim3(S_LEN/128, DIM/128), 128, G_SMEM>>>(
        attF, woutT, b_out, out, nullptr, nullptr, DIM, DIM);
}